// round 4
// baseline (speedup 1.0000x reference)
#include <cuda_runtime.h>
#include <math.h>

// Problem constants
#define BB    8
#define NSEQ  1024
#define DDIM  1024
#define NH    16
#define DHEAD 64
#define MROWS (BB * NSEQ)   // 8192

// ---------------- scratch (static device arrays; no cudaMalloc) -------------
__device__ float g_q [(size_t)MROWS * DDIM];
__device__ float g_k [(size_t)MROWS * DDIM];
__device__ float g_v [(size_t)MROWS * DDIM];
__device__ float g_ao[(size_t)MROWS * DDIM];
__device__ float g_h1[(size_t)MROWS * DDIM];
__device__ float g_t [(size_t)MROWS * DDIM];

// ---------------- SGEMM: C[M,1024] = A[M,1024] @ W[1024,1024] + bias --------
// EPI==0: C = A@W + b
// EPI==1: C = relu(A@W + b) + res   (res indexed same as C)
// Tile: BM=128, BN=128, BK=8, 256 threads, 8x8 microtile.
template <int EPI>
__global__ __launch_bounds__(256)
void sgemm_kernel(const float* __restrict__ A, const float* __restrict__ W,
                  const float* __restrict__ bias, const float* __restrict__ res,
                  float* __restrict__ C)
{
    __shared__ __align__(16) float As[8][128];
    __shared__ __align__(16) float Bs[8][128];

    const int tid = threadIdx.x;
    const int bm  = blockIdx.y * 128;
    const int bn  = blockIdx.x * 128;
    const int tx  = tid & 15;        // 0..15 -> cols (8 each)
    const int ty  = tid >> 4;        // 0..15 -> rows (8 each)

    // global load assignments
    const int arow  = tid >> 1;          // 0..127
    const int acol4 = (tid & 1) * 4;     // 0 or 4
    const int brow  = tid >> 5;          // 0..7
    const int bcol4 = (tid & 31) * 4;    // 0..124

    const float* Aptr = A + (size_t)(bm + arow) * DDIM;
    const float* Wptr = W + (size_t)brow * DDIM + bn + bcol4;

    float acc[8][8];
#pragma unroll
    for (int i = 0; i < 8; i++)
#pragma unroll
        for (int j = 0; j < 8; j++) acc[i][j] = 0.0f;

    for (int k0 = 0; k0 < DDIM; k0 += 8) {
        // load A tile (transposed into As) and B tile
        float4 av = *(const float4*)(Aptr + k0 + acol4);
        As[acol4 + 0][arow] = av.x;
        As[acol4 + 1][arow] = av.y;
        As[acol4 + 2][arow] = av.z;
        As[acol4 + 3][arow] = av.w;
        float4 bv = *(const float4*)(Wptr + (size_t)k0 * DDIM);
        *(float4*)&Bs[brow][bcol4] = bv;
        __syncthreads();

#pragma unroll
        for (int kk = 0; kk < 8; kk++) {
            float4 a0 = *(const float4*)&As[kk][ty * 8];
            float4 a1 = *(const float4*)&As[kk][ty * 8 + 4];
            float4 b0 = *(const float4*)&Bs[kk][tx * 8];
            float4 b1 = *(const float4*)&Bs[kk][tx * 8 + 4];
            float a[8] = {a0.x, a0.y, a0.z, a0.w, a1.x, a1.y, a1.z, a1.w};
            float b[8] = {b0.x, b0.y, b0.z, b0.w, b1.x, b1.y, b1.z, b1.w};
#pragma unroll
            for (int i = 0; i < 8; i++)
#pragma unroll
                for (int j = 0; j < 8; j++) acc[i][j] = fmaf(a[i], b[j], acc[i][j]);
        }
        __syncthreads();
    }

    // epilogue
    const int col0 = bn + tx * 8;
    float4 bsv0 = *(const float4*)(bias + col0);
    float4 bsv1 = *(const float4*)(bias + col0 + 4);
    float bvv[8] = {bsv0.x, bsv0.y, bsv0.z, bsv0.w, bsv1.x, bsv1.y, bsv1.z, bsv1.w};

#pragma unroll
    for (int i = 0; i < 8; i++) {
        const size_t row = (size_t)(bm + ty * 8 + i);
        float v[8];
#pragma unroll
        for (int j = 0; j < 8; j++) {
            float t = acc[i][j] + bvv[j];
            if (EPI == 1) t = fmaxf(t, 0.0f);
            v[j] = t;
        }
        if (EPI == 1) {
            float4 r0 = *(const float4*)(res + row * DDIM + col0);
            float4 r1 = *(const float4*)(res + row * DDIM + col0 + 4);
            v[0] += r0.x; v[1] += r0.y; v[2] += r0.z; v[3] += r0.w;
            v[4] += r1.x; v[5] += r1.y; v[6] += r1.z; v[7] += r1.w;
        }
        *(float4*)(C + row * DDIM + col0)     = make_float4(v[0], v[1], v[2], v[3]);
        *(float4*)(C + row * DDIM + col0 + 4) = make_float4(v[4], v[5], v[6], v[7]);
    }
}

// ---------------- Flash attention (fp32) -------------------------------------
// grid: (NSEQ/128, B*H); block: 256 threads (tx=tid&15 -> 4 k-cols, ty=tid>>4 -> 8 q-rows)
// smem strides of 68 floats (272B) keep every row 16B-aligned for LDS.128.
#define QS_STR 68
#define KS_STR 68
#define PS_STR 68
#define ATTN_SMEM_FLOATS (128 * QS_STR + 64 * KS_STR + 64 * 64 + 128 * PS_STR)
#define ATTN_SMEM_BYTES  (ATTN_SMEM_FLOATS * 4)

__global__ __launch_bounds__(256, 2)
void attn_kernel(const float* __restrict__ Q, const float* __restrict__ K,
                 const float* __restrict__ V, float* __restrict__ O)
{
    extern __shared__ float sm[];
    float* Qs = sm;                      // [128][68]
    float* Ks = Qs + 128 * QS_STR;       // [64][68]
    float* Vs = Ks + 64 * KS_STR;        // [64][64]
    float* Ps = Vs + 64 * 64;            // [128][68]

    const int tid = threadIdx.x;
    const int tx  = tid & 15;
    const int ty  = tid >> 4;
    const int bh  = blockIdx.y;
    const int b   = bh >> 4;
    const int h   = bh & 15;
    const int q0  = blockIdx.x * 128;

    const float* Qg = Q + ((size_t)(b * NSEQ + q0)) * DDIM + h * DHEAD;
    const float* Kg = K + ((size_t)(b * NSEQ)) * DDIM + h * DHEAD;
    const float* Vg = V + ((size_t)(b * NSEQ)) * DDIM + h * DHEAD;

    // load Q tile 128x64
    for (int l = tid; l < 128 * 16; l += 256) {
        int r  = l >> 4;
        int c4 = (l & 15) << 2;
        float4 v = *(const float4*)(Qg + (size_t)r * DDIM + c4);
        *(float4*)&Qs[r * QS_STR + c4] = v;
    }

    float mrow[8], lrow[8], o[8][4];
#pragma unroll
    for (int i = 0; i < 8; i++) {
        mrow[i] = -1e30f;
        lrow[i] = 0.0f;
#pragma unroll
        for (int j = 0; j < 4; j++) o[i][j] = 0.0f;
    }

    for (int kt = 0; kt < NSEQ / 64; kt++) {
        __syncthreads();   // prior PV done; Ks/Vs/Ps free
        const float* Kt = Kg + (size_t)(kt * 64) * DDIM;
        const float* Vt = Vg + (size_t)(kt * 64) * DDIM;
        for (int l = tid; l < 64 * 16; l += 256) {
            int r  = l >> 4;
            int c4 = (l & 15) << 2;
            float4 kv = *(const float4*)(Kt + (size_t)r * DDIM + c4);
            *(float4*)&Ks[r * KS_STR + c4] = kv;
            float4 vv = *(const float4*)(Vt + (size_t)r * DDIM + c4);
            *(float4*)&Vs[r * 64 + c4] = vv;
        }
        __syncthreads();

        // S = Q K^T  (8x4 microtile)
        float s[8][4];
#pragma unroll
        for (int i = 0; i < 8; i++)
#pragma unroll
            for (int j = 0; j < 4; j++) s[i][j] = 0.0f;

#pragma unroll 4
        for (int d4 = 0; d4 < 64; d4 += 4) {
            float4 bb[4];
#pragma unroll
            for (int j = 0; j < 4; j++)
                bb[j] = *(const float4*)&Ks[(tx * 4 + j) * KS_STR + d4];
#pragma unroll
            for (int i = 0; i < 8; i++) {
                float4 a = *(const float4*)&Qs[(ty * 8 + i) * QS_STR + d4];
#pragma unroll
                for (int j = 0; j < 4; j++) {
                    s[i][j] = fmaf(a.x, bb[j].x, s[i][j]);
                    s[i][j] = fmaf(a.y, bb[j].y, s[i][j]);
                    s[i][j] = fmaf(a.z, bb[j].z, s[i][j]);
                    s[i][j] = fmaf(a.w, bb[j].w, s[i][j]);
                }
            }
        }

        // online softmax (scale = 1/sqrt(1024) = 1/32), rows grouped over tx (16 lanes)
        const float scale = 0.03125f;
#pragma unroll
        for (int i = 0; i < 8; i++) {
            float mx = -1e30f;
#pragma unroll
            for (int j = 0; j < 4; j++) {
                s[i][j] *= scale;
                mx = fmaxf(mx, s[i][j]);
            }
            mx = fmaxf(mx, __shfl_xor_sync(0xffffffffu, mx, 8));
            mx = fmaxf(mx, __shfl_xor_sync(0xffffffffu, mx, 4));
            mx = fmaxf(mx, __shfl_xor_sync(0xffffffffu, mx, 2));
            mx = fmaxf(mx, __shfl_xor_sync(0xffffffffu, mx, 1));
            float mnew  = fmaxf(mrow[i], mx);
            float alpha = __expf(mrow[i] - mnew);
            float p0 = __expf(s[i][0] - mnew);
            float p1 = __expf(s[i][1] - mnew);
            float p2 = __expf(s[i][2] - mnew);
            float p3 = __expf(s[i][3] - mnew);
            *(float4*)&Ps[(ty * 8 + i) * PS_STR + tx * 4] = make_float4(p0, p1, p2, p3);
            float rs = p0 + p1 + p2 + p3;
            rs += __shfl_xor_sync(0xffffffffu, rs, 8);
            rs += __shfl_xor_sync(0xffffffffu, rs, 4);
            rs += __shfl_xor_sync(0xffffffffu, rs, 2);
            rs += __shfl_xor_sync(0xffffffffu, rs, 1);
            lrow[i] = lrow[i] * alpha + rs;
            mrow[i] = mnew;
#pragma unroll
            for (int j = 0; j < 4; j++) o[i][j] *= alpha;
        }
        __syncthreads();

        // O += P @ V
#pragma unroll 4
        for (int j4 = 0; j4 < 64; j4 += 4) {
            float4 v0 = *(const float4*)&Vs[(j4 + 0) * 64 + tx * 4];
            float4 v1 = *(const float4*)&Vs[(j4 + 1) * 64 + tx * 4];
            float4 v2 = *(const float4*)&Vs[(j4 + 2) * 64 + tx * 4];
            float4 v3 = *(const float4*)&Vs[(j4 + 3) * 64 + tx * 4];
#pragma unroll
            for (int i = 0; i < 8; i++) {
                float4 p = *(const float4*)&Ps[(ty * 8 + i) * PS_STR + j4];
                o[i][0] = fmaf(p.x, v0.x, fmaf(p.y, v1.x, fmaf(p.z, v2.x, fmaf(p.w, v3.x, o[i][0]))));
                o[i][1] = fmaf(p.x, v0.y, fmaf(p.y, v1.y, fmaf(p.z, v2.y, fmaf(p.w, v3.y, o[i][1]))));
                o[i][2] = fmaf(p.x, v0.z, fmaf(p.y, v1.z, fmaf(p.z, v2.z, fmaf(p.w, v3.z, o[i][2]))));
                o[i][3] = fmaf(p.x, v0.w, fmaf(p.y, v1.w, fmaf(p.z, v2.w, fmaf(p.w, v3.w, o[i][3]))));
            }
        }
    }

    float* Og = O + ((size_t)(b * NSEQ + q0 + ty * 8)) * DDIM + h * DHEAD + tx * 4;
#pragma unroll
    for (int i = 0; i < 8; i++) {
        float inv = 1.0f / lrow[i];
        *(float4*)(Og + (size_t)i * DDIM) =
            make_float4(o[i][0] * inv, o[i][1] * inv, o[i][2] * inv, o[i][3] * inv);
    }
}

// ---------------- LayerNorm: out = LN(A (+ R)) * g + beta -------------------
__global__ __launch_bounds__(256)
void ln_kernel(const float* __restrict__ A, const float* __restrict__ R,
               const float* __restrict__ gamma, const float* __restrict__ beta,
               float* __restrict__ out)
{
    const int row = blockIdx.x;
    const int tid = threadIdx.x;
    const size_t base = (size_t)row * DDIM + tid * 4;

    float4 v = *(const float4*)(A + base);
    if (R != nullptr) {
        float4 r = *(const float4*)(R + base);
        v.x += r.x; v.y += r.y; v.z += r.z; v.w += r.w;
    }

    __shared__ float red1[8];
    __shared__ float red2[8];

    float s = v.x + v.y + v.z + v.w;
#pragma unroll
    for (int off = 16; off > 0; off >>= 1) s += __shfl_xor_sync(0xffffffffu, s, off);
    if ((tid & 31) == 0) red1[tid >> 5] = s;
    __syncthreads();
    float tot = 0.0f;
#pragma unroll
    for (int k = 0; k < 8; k++) tot += red1[k];
    float mean = tot * (1.0f / 1024.0f);

    float d0 = v.x - mean, d1 = v.y - mean, d2 = v.z - mean, d3 = v.w - mean;
    float sq = d0 * d0 + d1 * d1 + d2 * d2 + d3 * d3;
#pragma unroll
    for (int off = 16; off > 0; off >>= 1) sq += __shfl_xor_sync(0xffffffffu, sq, off);
    if ((tid & 31) == 0) red2[tid >> 5] = sq;
    __syncthreads();
    float vtot = 0.0f;
#pragma unroll
    for (int k = 0; k < 8; k++) vtot += red2[k];
    float rstd = rsqrtf(vtot * (1.0f / 1024.0f) + 1e-6f);

    float4 g4 = *(const float4*)(gamma + tid * 4);
    float4 b4 = *(const float4*)(beta  + tid * 4);
    float4 o4 = make_float4(d0 * rstd * g4.x + b4.x,
                            d1 * rstd * g4.y + b4.y,
                            d2 * rstd * g4.z + b4.z,
                            d3 * rstd * g4.w + b4.w);
    *(float4*)(out + base) = o4;
}

// ---------------- launch -----------------------------------------------------
extern "C" void kernel_launch(void* const* d_in, const int* in_sizes, int n_in,
                              void* d_out, int out_size)
{
    (void)in_sizes; (void)n_in; (void)out_size;
    const float* x  = (const float*)d_in[0];
    const float* y  = (const float*)d_in[1];
    const float* Wq = (const float*)d_in[2];
    const float* bq = (const float*)d_in[3];
    const float* Wk = (const float*)d_in[4];
    const float* bk = (const float*)d_in[5];
    const float* Wv = (const float*)d_in[6];
    const float* bv = (const float*)d_in[7];
    const float* Wf = (const float*)d_in[8];
    const float* bf = (const float*)d_in[9];
    const float* g1 = (const float*)d_in[10];
    const float* b1 = (const float*)d_in[11];
    const float* g2 = (const float*)d_in[12];
    const float* b2 = (const float*)d_in[13];
    float* out = (float*)d_out;

    float *pq, *pk, *pv, *pao, *ph1, *pt;
    cudaGetSymbolAddress((void**)&pq,  g_q);
    cudaGetSymbolAddress((void**)&pk,  g_k);
    cudaGetSymbolAddress((void**)&pv,  g_v);
    cudaGetSymbolAddress((void**)&pao, g_ao);
    cudaGetSymbolAddress((void**)&ph1, g_h1);
    cudaGetSymbolAddress((void**)&pt,  g_t);

    cudaFuncSetAttribute(attn_kernel, cudaFuncAttributeMaxDynamicSharedMemorySize,
                         ATTN_SMEM_BYTES);

    dim3 gemm_grid(DDIM / 128, MROWS / 128);   // (8, 64)

    sgemm_kernel<0><<<gemm_grid, 256>>>(x, Wq, bq, nullptr, pq);
    sgemm_kernel<0><<<gemm_grid, 256>>>(y, Wk, bk, nullptr, pk);
    sgemm_kernel<0><<<gemm_grid, 256>>>(y, Wv, bv, nullptr, pv);

    attn_kernel<<<dim3(NSEQ / 128, BB * NH), 256, ATTN_SMEM_BYTES>>>(pq, pk, pv, pao);

    ln_kernel<<<MROWS, 256>>>(x, pao, g1, b1, ph1);

    sgemm_kernel<1><<<gemm_grid, 256>>>(ph1, Wf, bf, ph1, pt);

    ln_kernel<<<MROWS, 256>>>(pt, nullptr, g2, b2, out);
}

// round 6
// speedup vs baseline: 1.5059x; 1.5059x over previous
#include <cuda_runtime.h>
#include <cuda_bf16.h>
#include <math.h>
#include <stdint.h>

// Problem constants
#define BB    8
#define NSEQ  1024
#define DDIM  1024
#define NH    16
#define DHEAD 64
#define MROWS (BB * NSEQ)   // 8192

// ============================ PTX helpers ====================================
__device__ __forceinline__ uint32_t smem_u32(const void* p) {
    uint32_t a;
    asm("{ .reg .u64 t; cvta.to.shared.u64 t, %1; cvt.u32.u64 %0, t; }" : "=r"(a) : "l"(p));
    return a;
}
__device__ __forceinline__ void cp16(uint32_t d, const void* s) {
    asm volatile("cp.async.cg.shared.global [%0], [%1], 16;" :: "r"(d), "l"(s) : "memory");
}
#define CP_COMMIT() asm volatile("cp.async.commit_group;" ::: "memory")
#define CP_WAIT(n)  asm volatile("cp.async.wait_group %0;" :: "n"(n) : "memory")

__device__ __forceinline__ void ldsm4(uint32_t* r, uint32_t a) {
    asm volatile("ldmatrix.sync.aligned.m8n8.x4.shared.b16 {%0,%1,%2,%3}, [%4];"
        : "=r"(r[0]), "=r"(r[1]), "=r"(r[2]), "=r"(r[3]) : "r"(a));
}
__device__ __forceinline__ void mma16816(float* c, const uint32_t* a, const uint32_t* b) {
    asm volatile("mma.sync.aligned.m16n8k16.row.col.f32.bf16.bf16.f32 "
        "{%0,%1,%2,%3}, {%4,%5,%6,%7}, {%8,%9}, {%0,%1,%2,%3};"
        : "+f"(c[0]), "+f"(c[1]), "+f"(c[2]), "+f"(c[3])
        : "r"(a[0]), "r"(a[1]), "r"(a[2]), "r"(a[3]), "r"(b[0]), "r"(b[1]));
}

// ============================ scratch buffers ================================
__device__ float g_q [(size_t)MROWS * DDIM];
__device__ float g_k [(size_t)MROWS * DDIM];
__device__ float g_v [(size_t)MROWS * DDIM];
__device__ float g_ao[(size_t)MROWS * DDIM];
__device__ float g_h1[(size_t)MROWS * DDIM];
__device__ float g_t [(size_t)MROWS * DDIM];

__device__ __align__(1024) __nv_bfloat16 g_axh[(size_t)MROWS * DDIM];
__device__ __align__(1024) __nv_bfloat16 g_axl[(size_t)MROWS * DDIM];
__device__ __align__(1024) __nv_bfloat16 g_ayh[(size_t)MROWS * DDIM];
__device__ __align__(1024) __nv_bfloat16 g_ayl[(size_t)MROWS * DDIM];
__device__ __align__(1024) __nv_bfloat16 g_wth[4][(size_t)DDIM * DDIM];
__device__ __align__(1024) __nv_bfloat16 g_wtl[4][(size_t)DDIM * DDIM];

// ============================ split / transpose ==============================
__global__ __launch_bounds__(256)
void split_kernel(const float* __restrict__ in,
                  __nv_bfloat16* __restrict__ hi, __nv_bfloat16* __restrict__ lo)
{
    int i = blockIdx.x * 256 + threadIdx.x;   // float4 index; grid sized exactly
    float4 v = ((const float4*)in)[i];
    __nv_bfloat16 h0 = __float2bfloat16(v.x), h1 = __float2bfloat16(v.y);
    __nv_bfloat16 h2 = __float2bfloat16(v.z), h3 = __float2bfloat16(v.w);
    __nv_bfloat16 l0 = __float2bfloat16(v.x - __bfloat162float(h0));
    __nv_bfloat16 l1 = __float2bfloat16(v.y - __bfloat162float(h1));
    __nv_bfloat16 l2 = __float2bfloat16(v.z - __bfloat162float(h2));
    __nv_bfloat16 l3 = __float2bfloat16(v.w - __bfloat162float(h3));
    __nv_bfloat162 ha = __nv_bfloat162(h0, h1), hb = __nv_bfloat162(h2, h3);
    __nv_bfloat162 la = __nv_bfloat162(l0, l1), lb = __nv_bfloat162(l2, l3);
    uint2 hw, lw;
    hw.x = *(uint32_t*)&ha; hw.y = *(uint32_t*)&hb;
    lw.x = *(uint32_t*)&la; lw.y = *(uint32_t*)&lb;
    ((uint2*)hi)[i] = hw;
    ((uint2*)lo)[i] = lw;
}

// W[k][n] fp32 -> Wt_hi/lo[n][k] bf16
__global__ __launch_bounds__(256)
void tsplit_kernel(const float* __restrict__ W,
                   __nv_bfloat16* __restrict__ th, __nv_bfloat16* __restrict__ tl)
{
    __shared__ float t[32][33];
    const int tx = threadIdx.x & 31;
    const int ty = threadIdx.x >> 5;          // 0..7
    const int kb = blockIdx.y * 32;
    const int nb = blockIdx.x * 32;
#pragma unroll
    for (int i = 0; i < 4; i++) {
        int kk = ty + i * 8;
        t[kk][tx] = W[(size_t)(kb + kk) * DDIM + nb + tx];
    }
    __syncthreads();
#pragma unroll
    for (int i = 0; i < 4; i++) {
        int nn = ty + i * 8;
        float v = t[tx][nn];
        __nv_bfloat16 h = __float2bfloat16(v);
        __nv_bfloat16 l = __float2bfloat16(v - __bfloat162float(h));
        size_t o = (size_t)(nb + nn) * DDIM + kb + tx;
        th[o] = h; tl[o] = l;
    }
}

// ============================ HMMA GEMM (bf16 split, fp32 acc) ===============
// C[8192,1024] = A @ W + bias ; W given transposed: B[n][k].
// 3 passes: Ah*Bh + Al*Bh + Ah*Bl (Al*Bl dropped, ~2^-18 rel).
// BM=128, BN=128, BK=32, 256 thr, 8 warps of 64x32, 2-stage cp.async pipeline.
#define SST_B   80                    // smem row stride bytes (40 bf16) - conflict free
#define TILE_B  (128 * SST_B)         // 10240
#define STAGE_B (4 * TILE_B)          // 40960 : Ah,Al,Bh,Bl
#define GSMEM   (2 * STAGE_B)         // 81920

template <int EPI>
__global__ __launch_bounds__(256)
void gemm_mma(const __nv_bfloat16* __restrict__ Ah_, const __nv_bfloat16* __restrict__ Al_,
              const __nv_bfloat16* __restrict__ Bh_, const __nv_bfloat16* __restrict__ Bl_,
              const float* __restrict__ bias, const float* __restrict__ res,
              float* __restrict__ C)
{
    extern __shared__ __align__(128) char gsm[];
    const uint32_t sb = smem_u32(gsm);
    const int tid = threadIdx.x, lid = tid & 31, wid = tid >> 5;
    const int wm = (wid & 1) * 64, wn = (wid >> 1) * 32;
    const int bm = blockIdx.y * 128, bn = blockIdx.x * 128;

    // cp.async task mapping: 128 rows x 4 segs(16B); each thread: rows r, r+64
    const int row0 = tid >> 2, seg = tid & 3;
    const int row1 = row0 + 64;
    const size_t ga0 = (size_t)(bm + row0) * DDIM + seg * 8;
    const size_t ga1 = (size_t)(bm + row1) * DDIM + seg * 8;
    const size_t gb0 = (size_t)(bn + row0) * DDIM + seg * 8;
    const size_t gb1 = (size_t)(bn + row1) * DDIM + seg * 8;
    const uint32_t sd0 = (uint32_t)row0 * SST_B + seg * 16;
    const uint32_t sd1 = (uint32_t)row1 * SST_B + seg * 16;

    // ldmatrix lane offsets
    const uint32_t aoff = (uint32_t)(wm + (lid & 15)) * SST_B + (((lid >> 4) & 1) * 16);
    const uint32_t boff = (uint32_t)(wn + ((lid >> 4) & 1) * 8 + (lid & 7)) * SST_B
                        + (((lid >> 3) & 1) * 16);

    float acc[4][4][4];
#pragma unroll
    for (int i = 0; i < 4; i++)
#pragma unroll
        for (int t = 0; t < 4; t++)
#pragma unroll
            for (int e = 0; e < 4; e++) acc[i][t][e] = 0.0f;

    auto LOAD = [&](int st, int k0) {
        uint32_t s = sb + (uint32_t)st * STAGE_B;
        cp16(s + sd0,              Ah_ + ga0 + k0);
        cp16(s + sd1,              Ah_ + ga1 + k0);
        cp16(s + TILE_B + sd0,     Al_ + ga0 + k0);
        cp16(s + TILE_B + sd1,     Al_ + ga1 + k0);
        cp16(s + 2 * TILE_B + sd0, Bh_ + gb0 + k0);
        cp16(s + 2 * TILE_B + sd1, Bh_ + gb1 + k0);
        cp16(s + 3 * TILE_B + sd0, Bl_ + gb0 + k0);
        cp16(s + 3 * TILE_B + sd1, Bl_ + gb1 + k0);
    };

    LOAD(0, 0);
    CP_COMMIT();

    for (int c = 0; c < 32; c++) {
        if (c + 1 < 32) { LOAD((c + 1) & 1, (c + 1) * 32); CP_COMMIT(); CP_WAIT(1); }
        else            { CP_WAIT(0); }
        __syncthreads();
        const uint32_t st = sb + (uint32_t)(c & 1) * STAGE_B;

#pragma unroll
        for (int s = 0; s < 2; s++) {
            const uint32_t ks = s * 32;     // bytes (16 bf16)
            uint32_t AH[4][4], AL[4][4], B0[4], B1[4];
#pragma unroll
            for (int i = 0; i < 4; i++) ldsm4(AH[i], st + aoff + i * (16 * SST_B) + ks);
            ldsm4(B0, st + 2 * TILE_B + boff + ks);
            ldsm4(B1, st + 2 * TILE_B + boff + 16 * SST_B + ks);
#pragma unroll
            for (int i = 0; i < 4; i++) {
                mma16816(acc[i][0], AH[i], &B0[0]);
                mma16816(acc[i][1], AH[i], &B0[2]);
                mma16816(acc[i][2], AH[i], &B1[0]);
                mma16816(acc[i][3], AH[i], &B1[2]);
            }
#pragma unroll
            for (int i = 0; i < 4; i++) ldsm4(AL[i], st + TILE_B + aoff + i * (16 * SST_B) + ks);
#pragma unroll
            for (int i = 0; i < 4; i++) {
                mma16816(acc[i][0], AL[i], &B0[0]);
                mma16816(acc[i][1], AL[i], &B0[2]);
                mma16816(acc[i][2], AL[i], &B1[0]);
                mma16816(acc[i][3], AL[i], &B1[2]);
            }
            ldsm4(B0, st + 3 * TILE_B + boff + ks);
            ldsm4(B1, st + 3 * TILE_B + boff + 16 * SST_B + ks);
#pragma unroll
            for (int i = 0; i < 4; i++) {
                mma16816(acc[i][0], AH[i], &B0[0]);
                mma16816(acc[i][1], AH[i], &B0[2]);
                mma16816(acc[i][2], AH[i], &B1[0]);
                mma16816(acc[i][3], AH[i], &B1[2]);
            }
        }
        __syncthreads();
    }

    // epilogue
    const int gr = lid >> 2, gc = (lid & 3) * 2;
#pragma unroll
    for (int i = 0; i < 4; i++) {
        const int r0 = bm + wm + i * 16 + gr;
        const int r1 = r0 + 8;
#pragma unroll
        for (int t = 0; t < 4; t++) {
            const int col = bn + wn + t * 8 + gc;
            const float bx = bias[col], by = bias[col + 1];
            float v0 = acc[i][t][0] + bx, v1 = acc[i][t][1] + by;
            float v2 = acc[i][t][2] + bx, v3 = acc[i][t][3] + by;
            if (EPI == 1) {
                const float* rp0 = res + (size_t)r0 * DDIM + col;
                const float* rp1 = res + (size_t)r1 * DDIM + col;
                v0 = fmaxf(v0, 0.0f) + rp0[0];
                v1 = fmaxf(v1, 0.0f) + rp0[1];
                v2 = fmaxf(v2, 0.0f) + rp1[0];
                v3 = fmaxf(v3, 0.0f) + rp1[1];
            }
            *(float2*)(C + (size_t)r0 * DDIM + col) = make_float2(v0, v1);
            *(float2*)(C + (size_t)r1 * DDIM + col) = make_float2(v2, v3);
        }
    }
}

// ============================ Flash attention (fp32) =========================
#define QS_STR 68
#define KS_STR 68
#define PS_STR 68
#define ATTN_SMEM_FLOATS (128 * QS_STR + 64 * KS_STR + 64 * 64 + 128 * PS_STR)
#define ATTN_SMEM_BYTES  (ATTN_SMEM_FLOATS * 4)

__global__ __launch_bounds__(256, 2)
void attn_kernel(const float* __restrict__ Q, const float* __restrict__ K,
                 const float* __restrict__ V, float* __restrict__ O)
{
    extern __shared__ float sm[];
    float* Qs = sm;
    float* Ks = Qs + 128 * QS_STR;
    float* Vs = Ks + 64 * KS_STR;
    float* Ps = Vs + 64 * 64;

    const int tid = threadIdx.x;
    const int tx  = tid & 15;
    const int ty  = tid >> 4;
    const int bh  = blockIdx.y;
    const int b   = bh >> 4;
    const int h   = bh & 15;
    const int q0  = blockIdx.x * 128;

    const float* Qg = Q + ((size_t)(b * NSEQ + q0)) * DDIM + h * DHEAD;
    const float* Kg = K + ((size_t)(b * NSEQ)) * DDIM + h * DHEAD;
    const float* Vg = V + ((size_t)(b * NSEQ)) * DDIM + h * DHEAD;

    for (int l = tid; l < 128 * 16; l += 256) {
        int r  = l >> 4;
        int c4 = (l & 15) << 2;
        float4 v = *(const float4*)(Qg + (size_t)r * DDIM + c4);
        *(float4*)&Qs[r * QS_STR + c4] = v;
    }

    float mrow[8], lrow[8], o[8][4];
#pragma unroll
    for (int i = 0; i < 8; i++) {
        mrow[i] = -1e30f;
        lrow[i] = 0.0f;
#pragma unroll
        for (int j = 0; j < 4; j++) o[i][j] = 0.0f;
    }

    for (int kt = 0; kt < NSEQ / 64; kt++) {
        __syncthreads();
        const float* Kt = Kg + (size_t)(kt * 64) * DDIM;
        const float* Vt = Vg + (size_t)(kt * 64) * DDIM;
        for (int l = tid; l < 64 * 16; l += 256) {
            int r  = l >> 4;
            int c4 = (l & 15) << 2;
            float4 kv = *(const float4*)(Kt + (size_t)r * DDIM + c4);
            *(float4*)&Ks[r * KS_STR + c4] = kv;
            float4 vv = *(const float4*)(Vt + (size_t)r * DDIM + c4);
            *(float4*)&Vs[r * 64 + c4] = vv;
        }
        __syncthreads();

        float s[8][4];
#pragma unroll
        for (int i = 0; i < 8; i++)
#pragma unroll
            for (int j = 0; j < 4; j++) s[i][j] = 0.0f;

#pragma unroll 4
        for (int d4 = 0; d4 < 64; d4 += 4) {
            float4 bb[4];
#pragma unroll
            for (int j = 0; j < 4; j++)
                bb[j] = *(const float4*)&Ks[(tx * 4 + j) * KS_STR + d4];
#pragma unroll
            for (int i = 0; i < 8; i++) {
                float4 a = *(const float4*)&Qs[(ty * 8 + i) * QS_STR + d4];
#pragma unroll
                for (int j = 0; j < 4; j++) {
                    s[i][j] = fmaf(a.x, bb[j].x, s[i][j]);
                    s[i][j] = fmaf(a.y, bb[j].y, s[i][j]);
                    s[i][j] = fmaf(a.z, bb[j].z, s[i][j]);
                    s[i][j] = fmaf(a.w, bb[j].w, s[i][j]);
                }
            }
        }

        const float scale = 0.03125f;
#pragma unroll
        for (int i = 0; i < 8; i++) {
            float mx = -1e30f;
#pragma unroll
            for (int j = 0; j < 4; j++) {
                s[i][j] *= scale;
                mx = fmaxf(mx, s[i][j]);
            }
            mx = fmaxf(mx, __shfl_xor_sync(0xffffffffu, mx, 8));
            mx = fmaxf(mx, __shfl_xor_sync(0xffffffffu, mx, 4));
            mx = fmaxf(mx, __shfl_xor_sync(0xffffffffu, mx, 2));
            mx = fmaxf(mx, __shfl_xor_sync(0xffffffffu, mx, 1));
            float mnew  = fmaxf(mrow[i], mx);
            float alpha = __expf(mrow[i] - mnew);
            float p0 = __expf(s[i][0] - mnew);
            float p1 = __expf(s[i][1] - mnew);
            float p2 = __expf(s[i][2] - mnew);
            float p3 = __expf(s[i][3] - mnew);
            *(float4*)&Ps[(ty * 8 + i) * PS_STR + tx * 4] = make_float4(p0, p1, p2, p3);
            float rs = p0 + p1 + p2 + p3;
            rs += __shfl_xor_sync(0xffffffffu, rs, 8);
            rs += __shfl_xor_sync(0xffffffffu, rs, 4);
            rs += __shfl_xor_sync(0xffffffffu, rs, 2);
            rs += __shfl_xor_sync(0xffffffffu, rs, 1);
            lrow[i] = lrow[i] * alpha + rs;
            mrow[i] = mnew;
#pragma unroll
            for (int j = 0; j < 4; j++) o[i][j] *= alpha;
        }
        __syncthreads();

#pragma unroll 4
        for (int j4 = 0; j4 < 64; j4 += 4) {
            float4 v0 = *(const float4*)&Vs[(j4 + 0) * 64 + tx * 4];
            float4 v1 = *(const float4*)&Vs[(j4 + 1) * 64 + tx * 4];
            float4 v2 = *(const float4*)&Vs[(j4 + 2) * 64 + tx * 4];
            float4 v3 = *(const float4*)&Vs[(j4 + 3) * 64 + tx * 4];
#pragma unroll
            for (int i = 0; i < 8; i++) {
                float4 p = *(const float4*)&Ps[(ty * 8 + i) * PS_STR + j4];
                o[i][0] = fmaf(p.x, v0.x, fmaf(p.y, v1.x, fmaf(p.z, v2.x, fmaf(p.w, v3.x, o[i][0]))));
                o[i][1] = fmaf(p.x, v0.y, fmaf(p.y, v1.y, fmaf(p.z, v2.y, fmaf(p.w, v3.y, o[i][1]))));
                o[i][2] = fmaf(p.x, v0.z, fmaf(p.y, v1.z, fmaf(p.z, v2.z, fmaf(p.w, v3.z, o[i][2]))));
                o[i][3] = fmaf(p.x, v0.w, fmaf(p.y, v1.w, fmaf(p.z, v2.w, fmaf(p.w, v3.w, o[i][3]))));
            }
        }
    }

    float* Og = O + ((size_t)(b * NSEQ + q0 + ty * 8)) * DDIM + h * DHEAD + tx * 4;
#pragma unroll
    for (int i = 0; i < 8; i++) {
        float inv = 1.0f / lrow[i];
        *(float4*)(Og + (size_t)i * DDIM) =
            make_float4(o[i][0] * inv, o[i][1] * inv, o[i][2] * inv, o[i][3] * inv);
    }
}

// ============================ LayerNorm (+ optional bf16 split out) ==========
__global__ __launch_bounds__(256)
void ln_kernel(const float* __restrict__ A, const float* __restrict__ R,
               const float* __restrict__ gamma, const float* __restrict__ beta,
               float* __restrict__ out,
               __nv_bfloat16* __restrict__ hi, __nv_bfloat16* __restrict__ lo)
{
    const int row = blockIdx.x;
    const int tid = threadIdx.x;
    const size_t base = (size_t)row * DDIM + tid * 4;

    float4 v = *(const float4*)(A + base);
    if (R != nullptr) {
        float4 r = *(const float4*)(R + base);
        v.x += r.x; v.y += r.y; v.z += r.z; v.w += r.w;
    }

    __shared__ float red1[8];
    __shared__ float red2[8];

    float s = v.x + v.y + v.z + v.w;
#pragma unroll
    for (int off = 16; off > 0; off >>= 1) s += __shfl_xor_sync(0xffffffffu, s, off);
    if ((tid & 31) == 0) red1[tid >> 5] = s;
    __syncthreads();
    float tot = 0.0f;
#pragma unroll
    for (int k = 0; k < 8; k++) tot += red1[k];
    float mean = tot * (1.0f / 1024.0f);

    float d0 = v.x - mean, d1 = v.y - mean, d2 = v.z - mean, d3 = v.w - mean;
    float sq = d0 * d0 + d1 * d1 + d2 * d2 + d3 * d3;
#pragma unroll
    for (int off = 16; off > 0; off >>= 1) sq += __shfl_xor_sync(0xffffffffu, sq, off);
    if ((tid & 31) == 0) red2[tid >> 5] = sq;
    __syncthreads();
    float vtot = 0.0f;
#pragma unroll
    for (int k = 0; k < 8; k++) vtot += red2[k];
    float rstd = rsqrtf(vtot * (1.0f / 1024.0f) + 1e-6f);

    float4 g4 = *(const float4*)(gamma + tid * 4);
    float4 b4 = *(const float4*)(beta  + tid * 4);
    float4 o4 = make_float4(d0 * rstd * g4.x + b4.x,
                            d1 * rstd * g4.y + b4.y,
                            d2 * rstd * g4.z + b4.z,
                            d3 * rstd * g4.w + b4.w);
    *(float4*)(out + base) = o4;

    if (hi != nullptr) {
        __nv_bfloat16 h0 = __float2bfloat16(o4.x), h1 = __float2bfloat16(o4.y);
        __nv_bfloat16 h2 = __float2bfloat16(o4.z), h3 = __float2bfloat16(o4.w);
        __nv_bfloat16 l0 = __float2bfloat16(o4.x - __bfloat162float(h0));
        __nv_bfloat16 l1 = __float2bfloat16(o4.y - __bfloat162float(h1));
        __nv_bfloat16 l2 = __float2bfloat16(o4.z - __bfloat162float(h2));
        __nv_bfloat16 l3 = __float2bfloat16(o4.w - __bfloat162float(h3));
        __nv_bfloat162 hA(h0, h1), hB(h2, h3), lA(l0, l1), lB(l2, l3);
        uint2 hw, lw;
        hw.x = *(uint32_t*)&hA; hw.y = *(uint32_t*)&hB;
        lw.x = *(uint32_t*)&lA; lw.y = *(uint32_t*)&lB;
        *(uint2*)(hi + base) = hw;
        *(uint2*)(lo + base) = lw;
    }
}

// ============================ host launch ====================================
extern "C" void kernel_launch(void* const* d_in, const int* in_sizes, int n_in,
                              void* d_out, int out_size)
{
    (void)in_sizes; (void)n_in; (void)out_size;
    const float* x  = (const float*)d_in[0];
    const float* y  = (const float*)d_in[1];
    const float* Wq = (const float*)d_in[2];
    const float* bq = (const float*)d_in[3];
    const float* Wk = (const float*)d_in[4];
    const float* bk = (const float*)d_in[5];
    const float* Wv = (const float*)d_in[6];
    const float* bv = (const float*)d_in[7];
    const float* Wf = (const float*)d_in[8];
    const float* bf = (const float*)d_in[9];
    const float* g1 = (const float*)d_in[10];
    const float* b1 = (const float*)d_in[11];
    const float* g2 = (const float*)d_in[12];
    const float* b2 = (const float*)d_in[13];
    float* out = (float*)d_out;

    float *pq, *pk, *pv, *pao, *ph1, *pt;
    cudaGetSymbolAddress((void**)&pq,  g_q);
    cudaGetSymbolAddress((void**)&pk,  g_k);
    cudaGetSymbolAddress((void**)&pv,  g_v);
    cudaGetSymbolAddress((void**)&pao, g_ao);
    cudaGetSymbolAddress((void**)&ph1, g_h1);
    cudaGetSymbolAddress((void**)&pt,  g_t);

    void *paxh, *paxl, *payh, *payl, *pwth, *pwtl;
    cudaGetSymbolAddress(&paxh, g_axh);
    cudaGetSymbolAddress(&paxl, g_axl);
    cudaGetSymbolAddress(&payh, g_ayh);
    cudaGetSymbolAddress(&payl, g_ayl);
    cudaGetSymbolAddress(&pwth, g_wth);
    cudaGetSymbolAddress(&pwtl, g_wtl);

    __nv_bfloat16* axh = (__nv_bfloat16*)paxh;
    __nv_bfloat16* axl = (__nv_bfloat16*)paxl;
    __nv_bfloat16* ayh = (__nv_bfloat16*)payh;
    __nv_bfloat16* ayl = (__nv_bfloat16*)payl;
    __nv_bfloat16* wth = (__nv_bfloat16*)pwth;
    __nv_bfloat16* wtl = (__nv_bfloat16*)pwtl;
    const size_t WSZ = (size_t)DDIM * DDIM;

    cudaFuncSetAttribute(gemm_mma<0>, cudaFuncAttributeMaxDynamicSharedMemorySize, GSMEM);
    cudaFuncSetAttribute(gemm_mma<1>, cudaFuncAttributeMaxDynamicSharedMemorySize, GSMEM);
    cudaFuncSetAttribute(attn_kernel, cudaFuncAttributeMaxDynamicSharedMemorySize, ATTN_SMEM_BYTES);

    const int split_grid = (MROWS * DDIM) / 4 / 256;  // 8192
    dim3 tgrid(32, 32), tblk(256);
    dim3 ggrid(DDIM / 128, MROWS / 128);               // (8, 64)

    // prep: splits + weight transposes
    split_kernel<<<split_grid, 256>>>(x, axh, axl);
    split_kernel<<<split_grid, 256>>>(y, ayh, ayl);
    tsplit_kernel<<<tgrid, tblk>>>(Wq, wth + 0 * WSZ, wtl + 0 * WSZ);
    tsplit_kernel<<<tgrid, tblk>>>(Wk, wth + 1 * WSZ, wtl + 1 * WSZ);
    tsplit_kernel<<<tgrid, tblk>>>(Wv, wth + 2 * WSZ, wtl + 2 * WSZ);
    tsplit_kernel<<<tgrid, tblk>>>(Wf, wth + 3 * WSZ, wtl + 3 * WSZ);

    // projections (HMMA tensor cores)
    gemm_mma<0><<<ggrid, 256, GSMEM>>>(axh, axl, wth + 0 * WSZ, wtl + 0 * WSZ, bq, nullptr, pq);
    gemm_mma<0><<<ggrid, 256, GSMEM>>>(ayh, ayl, wth + 1 * WSZ, wtl + 1 * WSZ, bk, nullptr, pk);
    gemm_mma<0><<<ggrid, 256, GSMEM>>>(ayh, ayl, wth + 2 * WSZ, wtl + 2 * WSZ, bv, nullptr, pv);

    // attention (fp32 flash)
    attn_kernel<<<dim3(NSEQ / 128, BB * NH), 256, ATTN_SMEM_BYTES>>>(pq, pk, pv, pao);

    // LN1(x + attn) -> fp32 h1 AND bf16 hi/lo split (reuses ax buffers)
    ln_kernel<<<MROWS, 256>>>(x, pao, g1, b1, ph1, axh, axl);

    // FF: t = relu(h1 @ Wf + bf) + h1
    gemm_mma<1><<<ggrid, 256, GSMEM>>>(axh, axl, wth + 3 * WSZ, wtl + 3 * WSZ, bf, ph1, pt);

    // LN2
    ln_kernel<<<MROWS, 256>>>(pt, nullptr, g2, b2, out, nullptr, nullptr);
}

// round 7
// speedup vs baseline: 2.4417x; 1.6214x over previous
#include <cuda_runtime.h>
#include <cuda_bf16.h>
#include <math.h>
#include <stdint.h>

// Problem constants
#define BB    8
#define NSEQ  1024
#define DDIM  1024
#define NH    16
#define DHEAD 64
#define MROWS (BB * NSEQ)   // 8192

// ============================ PTX helpers ====================================
__device__ __forceinline__ uint32_t smem_u32(const void* p) {
    uint32_t a;
    asm("{ .reg .u64 t; cvta.to.shared.u64 t, %1; cvt.u32.u64 %0, t; }" : "=r"(a) : "l"(p));
    return a;
}
__device__ __forceinline__ void cp16(uint32_t d, const void* s) {
    asm volatile("cp.async.cg.shared.global [%0], [%1], 16;" :: "r"(d), "l"(s) : "memory");
}
#define CP_COMMIT() asm volatile("cp.async.commit_group;" ::: "memory")
#define CP_WAIT(n)  asm volatile("cp.async.wait_group %0;" :: "n"(n) : "memory")

__device__ __forceinline__ void ldsm4(uint32_t* r, uint32_t a) {
    asm volatile("ldmatrix.sync.aligned.m8n8.x4.shared.b16 {%0,%1,%2,%3}, [%4];"
        : "=r"(r[0]), "=r"(r[1]), "=r"(r[2]), "=r"(r[3]) : "r"(a));
}
__device__ __forceinline__ void ldsm4t(uint32_t* r, uint32_t a) {
    asm volatile("ldmatrix.sync.aligned.m8n8.x4.trans.shared.b16 {%0,%1,%2,%3}, [%4];"
        : "=r"(r[0]), "=r"(r[1]), "=r"(r[2]), "=r"(r[3]) : "r"(a));
}
__device__ __forceinline__ void mma16816(float* c, const uint32_t* a, const uint32_t* b) {
    asm volatile("mma.sync.aligned.m16n8k16.row.col.f32.bf16.bf16.f32 "
        "{%0,%1,%2,%3}, {%4,%5,%6,%7}, {%8,%9}, {%0,%1,%2,%3};"
        : "+f"(c[0]), "+f"(c[1]), "+f"(c[2]), "+f"(c[3])
        : "r"(a[0]), "r"(a[1]), "r"(a[2]), "r"(a[3]), "r"(b[0]), "r"(b[1]));
}
__device__ __forceinline__ void hi_lo_pack(float x, float y, uint32_t& h, uint32_t& l) {
    __nv_bfloat16 hx = __float2bfloat16(x), hy = __float2bfloat16(y);
    __nv_bfloat16 lx = __float2bfloat16(x - __bfloat162float(hx));
    __nv_bfloat16 ly = __float2bfloat16(y - __bfloat162float(hy));
    __nv_bfloat162 hv(hx, hy), lv(lx, ly);
    h = *(uint32_t*)&hv; l = *(uint32_t*)&lv;
}

// ============================ scratch buffers ================================
__device__ float g_ao[(size_t)MROWS * DDIM];
__device__ float g_h1[(size_t)MROWS * DDIM];
__device__ float g_t [(size_t)MROWS * DDIM];

__device__ __align__(1024) __nv_bfloat16 g_axh[(size_t)MROWS * DDIM];
__device__ __align__(1024) __nv_bfloat16 g_axl[(size_t)MROWS * DDIM];
__device__ __align__(1024) __nv_bfloat16 g_ayh[(size_t)MROWS * DDIM];
__device__ __align__(1024) __nv_bfloat16 g_ayl[(size_t)MROWS * DDIM];
__device__ __align__(1024) __nv_bfloat16 g_wth[4][(size_t)DDIM * DDIM];
__device__ __align__(1024) __nv_bfloat16 g_wtl[4][(size_t)DDIM * DDIM];
// QKV hi/lo outputs of the projection GEMMs
__device__ __align__(1024) __nv_bfloat16 g_qh[(size_t)MROWS * DDIM];
__device__ __align__(1024) __nv_bfloat16 g_ql[(size_t)MROWS * DDIM];
__device__ __align__(1024) __nv_bfloat16 g_kh[(size_t)MROWS * DDIM];
__device__ __align__(1024) __nv_bfloat16 g_kl[(size_t)MROWS * DDIM];
__device__ __align__(1024) __nv_bfloat16 g_vh[(size_t)MROWS * DDIM];
__device__ __align__(1024) __nv_bfloat16 g_vl[(size_t)MROWS * DDIM];

// ============================ split / transpose ==============================
__global__ __launch_bounds__(256)
void split_kernel(const float* __restrict__ in,
                  __nv_bfloat16* __restrict__ hi, __nv_bfloat16* __restrict__ lo)
{
    int i = blockIdx.x * 256 + threadIdx.x;
    float4 v = ((const float4*)in)[i];
    __nv_bfloat16 h0 = __float2bfloat16(v.x), h1 = __float2bfloat16(v.y);
    __nv_bfloat16 h2 = __float2bfloat16(v.z), h3 = __float2bfloat16(v.w);
    __nv_bfloat16 l0 = __float2bfloat16(v.x - __bfloat162float(h0));
    __nv_bfloat16 l1 = __float2bfloat16(v.y - __bfloat162float(h1));
    __nv_bfloat16 l2 = __float2bfloat16(v.z - __bfloat162float(h2));
    __nv_bfloat16 l3 = __float2bfloat16(v.w - __bfloat162float(h3));
    __nv_bfloat162 ha(h0, h1), hb(h2, h3), la(l0, l1), lb(l2, l3);
    uint2 hw, lw;
    hw.x = *(uint32_t*)&ha; hw.y = *(uint32_t*)&hb;
    lw.x = *(uint32_t*)&la; lw.y = *(uint32_t*)&lb;
    ((uint2*)hi)[i] = hw;
    ((uint2*)lo)[i] = lw;
}

// W[k][n] fp32 -> Wt_hi/lo[n][k] bf16
__global__ __launch_bounds__(256)
void tsplit_kernel(const float* __restrict__ W,
                   __nv_bfloat16* __restrict__ th, __nv_bfloat16* __restrict__ tl)
{
    __shared__ float t[32][33];
    const int tx = threadIdx.x & 31;
    const int ty = threadIdx.x >> 5;
    const int kb = blockIdx.y * 32;
    const int nb = blockIdx.x * 32;
#pragma unroll
    for (int i = 0; i < 4; i++) {
        int kk = ty + i * 8;
        t[kk][tx] = W[(size_t)(kb + kk) * DDIM + nb + tx];
    }
    __syncthreads();
#pragma unroll
    for (int i = 0; i < 4; i++) {
        int nn = ty + i * 8;
        float v = t[tx][nn];
        __nv_bfloat16 h = __float2bfloat16(v);
        __nv_bfloat16 l = __float2bfloat16(v - __bfloat162float(h));
        size_t o = (size_t)(nb + nn) * DDIM + kb + tx;
        th[o] = h; tl[o] = l;
    }
}

// ============================ HMMA GEMM (bf16 split, fp32 acc) ===============
// EPI 0: C = A@W + b (fp32). EPI 1: C = relu(A@W+b)+res (fp32).
// EPI 2: hi/lo bf16 split of (A@W + b) -> Ch, Cl.
#define SST_B   80
#define TILE_B  (128 * SST_B)
#define STAGE_B (4 * TILE_B)
#define GSMEM   (2 * STAGE_B)

template <int EPI>
__global__ __launch_bounds__(256)
void gemm_mma(const __nv_bfloat16* __restrict__ Ah_, const __nv_bfloat16* __restrict__ Al_,
              const __nv_bfloat16* __restrict__ Bh_, const __nv_bfloat16* __restrict__ Bl_,
              const float* __restrict__ bias, const float* __restrict__ res,
              float* __restrict__ C,
              __nv_bfloat16* __restrict__ Ch, __nv_bfloat16* __restrict__ Cl)
{
    extern __shared__ __align__(128) char gsm[];
    const uint32_t sb = smem_u32(gsm);
    const int tid = threadIdx.x, lid = tid & 31, wid = tid >> 5;
    const int wm = (wid & 1) * 64, wn = (wid >> 1) * 32;
    const int bm = blockIdx.y * 128, bn = blockIdx.x * 128;

    const int row0 = tid >> 2, seg = tid & 3;
    const int row1 = row0 + 64;
    const size_t ga0 = (size_t)(bm + row0) * DDIM + seg * 8;
    const size_t ga1 = (size_t)(bm + row1) * DDIM + seg * 8;
    const size_t gb0 = (size_t)(bn + row0) * DDIM + seg * 8;
    const size_t gb1 = (size_t)(bn + row1) * DDIM + seg * 8;
    const uint32_t sd0 = (uint32_t)row0 * SST_B + seg * 16;
    const uint32_t sd1 = (uint32_t)row1 * SST_B + seg * 16;

    const uint32_t aoff = (uint32_t)(wm + (lid & 15)) * SST_B + (((lid >> 4) & 1) * 16);
    const uint32_t boff = (uint32_t)(wn + ((lid >> 4) & 1) * 8 + (lid & 7)) * SST_B
                        + (((lid >> 3) & 1) * 16);

    float acc[4][4][4];
#pragma unroll
    for (int i = 0; i < 4; i++)
#pragma unroll
        for (int t = 0; t < 4; t++)
#pragma unroll
            for (int e = 0; e < 4; e++) acc[i][t][e] = 0.0f;

    auto LOAD = [&](int st, int k0) {
        uint32_t s = sb + (uint32_t)st * STAGE_B;
        cp16(s + sd0,              Ah_ + ga0 + k0);
        cp16(s + sd1,              Ah_ + ga1 + k0);
        cp16(s + TILE_B + sd0,     Al_ + ga0 + k0);
        cp16(s + TILE_B + sd1,     Al_ + ga1 + k0);
        cp16(s + 2 * TILE_B + sd0, Bh_ + gb0 + k0);
        cp16(s + 2 * TILE_B + sd1, Bh_ + gb1 + k0);
        cp16(s + 3 * TILE_B + sd0, Bl_ + gb0 + k0);
        cp16(s + 3 * TILE_B + sd1, Bl_ + gb1 + k0);
    };

    LOAD(0, 0);
    CP_COMMIT();

    for (int c = 0; c < 32; c++) {
        if (c + 1 < 32) { LOAD((c + 1) & 1, (c + 1) * 32); CP_COMMIT(); CP_WAIT(1); }
        else            { CP_WAIT(0); }
        __syncthreads();
        const uint32_t st = sb + (uint32_t)(c & 1) * STAGE_B;

#pragma unroll
        for (int s = 0; s < 2; s++) {
            const uint32_t ks = s * 32;
            uint32_t AH[4][4], AL[4][4], B0[4], B1[4];
#pragma unroll
            for (int i = 0; i < 4; i++) ldsm4(AH[i], st + aoff + i * (16 * SST_B) + ks);
            ldsm4(B0, st + 2 * TILE_B + boff + ks);
            ldsm4(B1, st + 2 * TILE_B + boff + 16 * SST_B + ks);
#pragma unroll
            for (int i = 0; i < 4; i++) {
                mma16816(acc[i][0], AH[i], &B0[0]);
                mma16816(acc[i][1], AH[i], &B0[2]);
                mma16816(acc[i][2], AH[i], &B1[0]);
                mma16816(acc[i][3], AH[i], &B1[2]);
            }
#pragma unroll
            for (int i = 0; i < 4; i++) ldsm4(AL[i], st + TILE_B + aoff + i * (16 * SST_B) + ks);
#pragma unroll
            for (int i = 0; i < 4; i++) {
                mma16816(acc[i][0], AL[i], &B0[0]);
                mma16816(acc[i][1], AL[i], &B0[2]);
                mma16816(acc[i][2], AL[i], &B1[0]);
                mma16816(acc[i][3], AL[i], &B1[2]);
            }
            ldsm4(B0, st + 3 * TILE_B + boff + ks);
            ldsm4(B1, st + 3 * TILE_B + boff + 16 * SST_B + ks);
#pragma unroll
            for (int i = 0; i < 4; i++) {
                mma16816(acc[i][0], AH[i], &B0[0]);
                mma16816(acc[i][1], AH[i], &B0[2]);
                mma16816(acc[i][2], AH[i], &B1[0]);
                mma16816(acc[i][3], AH[i], &B1[2]);
            }
        }
        __syncthreads();
    }

    const int gr = lid >> 2, gc = (lid & 3) * 2;
#pragma unroll
    for (int i = 0; i < 4; i++) {
        const int r0 = bm + wm + i * 16 + gr;
        const int r1 = r0 + 8;
#pragma unroll
        for (int t = 0; t < 4; t++) {
            const int col = bn + wn + t * 8 + gc;
            const float bx = bias[col], by = bias[col + 1];
            float v0 = acc[i][t][0] + bx, v1 = acc[i][t][1] + by;
            float v2 = acc[i][t][2] + bx, v3 = acc[i][t][3] + by;
            if (EPI == 2) {
                uint32_t h01, l01, h23, l23;
                hi_lo_pack(v0, v1, h01, l01);
                hi_lo_pack(v2, v3, h23, l23);
                *(uint32_t*)(Ch + (size_t)r0 * DDIM + col) = h01;
                *(uint32_t*)(Cl + (size_t)r0 * DDIM + col) = l01;
                *(uint32_t*)(Ch + (size_t)r1 * DDIM + col) = h23;
                *(uint32_t*)(Cl + (size_t)r1 * DDIM + col) = l23;
            } else {
                if (EPI == 1) {
                    const float* rp0 = res + (size_t)r0 * DDIM + col;
                    const float* rp1 = res + (size_t)r1 * DDIM + col;
                    v0 = fmaxf(v0, 0.0f) + rp0[0];
                    v1 = fmaxf(v1, 0.0f) + rp0[1];
                    v2 = fmaxf(v2, 0.0f) + rp1[0];
                    v3 = fmaxf(v3, 0.0f) + rp1[1];
                }
                *(float2*)(C + (size_t)r0 * DDIM + col) = make_float2(v0, v1);
                *(float2*)(C + (size_t)r1 * DDIM + col) = make_float2(v2, v3);
            }
        }
    }
}

// ============================ HMMA flash attention ===========================
// CTA: 128 q-rows of one (b,h). 8 warps x 16 rows. K/V chunks of 128, 2-stage.
// S = QK^T 3-pass split; softmax fp32 on fragments; P.V 3-pass split.
#define AST_B   144                    // smem row stride bytes (72 bf16)
#define ATILE_B (128 * AST_B)          // 18432
#define ASMEM   (10 * ATILE_B)         // 184320: Qh,Ql + 2 stages x (Kh,Kl,Vh,Vl)

__global__ __launch_bounds__(256, 1)
void attn_mma(const __nv_bfloat16* __restrict__ Qh_g, const __nv_bfloat16* __restrict__ Ql_g,
              const __nv_bfloat16* __restrict__ Kh_g, const __nv_bfloat16* __restrict__ Kl_g,
              const __nv_bfloat16* __restrict__ Vh_g, const __nv_bfloat16* __restrict__ Vl_g,
              float* __restrict__ O)
{
    extern __shared__ __align__(128) char asm_[];
    const uint32_t sb = smem_u32(asm_);
    const int tid = threadIdx.x, lid = tid & 31, wid = tid >> 5;
    const int bh = blockIdx.y, b = bh >> 4, h = bh & 15;
    const int q0 = blockIdx.x * 128;

    const size_t qbase = (size_t)(b * NSEQ + q0) * DDIM + h * DHEAD;
    const size_t kbase = (size_t)(b * NSEQ) * DDIM + h * DHEAD;

    const uint32_t sQh = sb, sQl = sb + ATILE_B;
    // ldmatrix offsets
    const uint32_t aoff = (uint32_t)(16 * wid + (lid & 15)) * AST_B + ((lid >> 4) & 1) * 16;
    const uint32_t boff = (uint32_t)(((lid >> 4) & 1) * 8 + (lid & 7)) * AST_B
                        + ((lid >> 3) & 1) * 16;
    const uint32_t voff = (uint32_t)(lid & 15) * AST_B + ((lid >> 4) & 1) * 16;

    auto loadKV = [&](int kt, int st) {
        const uint32_t base = sb + 2 * ATILE_B + (uint32_t)st * (4 * ATILE_B);
        const size_t gk = kbase + (size_t)(kt * 128) * DDIM;
        for (int i = tid; i < 1024; i += 256) {
            int r = i >> 3, sg = i & 7;
            uint32_t so = (uint32_t)r * AST_B + sg * 16;
            size_t go = gk + (size_t)r * DDIM + sg * 8;
            cp16(base + so,               Kh_g + go);
            cp16(base + ATILE_B + so,     Kl_g + go);
            cp16(base + 2 * ATILE_B + so, Vh_g + go);
            cp16(base + 3 * ATILE_B + so, Vl_g + go);
        }
    };

    // prologue: Q + KV0 (group 0), KV1 (group 1)
    for (int i = tid; i < 1024; i += 256) {
        int r = i >> 3, sg = i & 7;
        uint32_t so = (uint32_t)r * AST_B + sg * 16;
        size_t go = qbase + (size_t)r * DDIM + sg * 8;
        cp16(sQh + so, Qh_g + go);
        cp16(sQl + so, Ql_g + go);
    }
    loadKV(0, 0);
    CP_COMMIT();
    loadKV(1, 1);
    CP_COMMIT();
    CP_WAIT(1);
    __syncthreads();

    float m0 = -1e30f, m1 = -1e30f, l0v = 0.0f, l1v = 0.0f;
    float ov[8][4];
#pragma unroll
    for (int j = 0; j < 8; j++)
#pragma unroll
        for (int e = 0; e < 4; e++) ov[j][e] = 0.0f;

    for (int kt = 0; kt < 8; kt++) {
        const uint32_t kvb = sb + 2 * ATILE_B + (uint32_t)(kt & 1) * (4 * ATILE_B);

        // ---- S = Q K^T (3-pass) ----
        float sacc[16][4];
#pragma unroll
        for (int t = 0; t < 16; t++)
#pragma unroll
            for (int e = 0; e < 4; e++) sacc[t][e] = 0.0f;

#pragma unroll
        for (int kk = 0; kk < 4; kk++) {
            uint32_t QH[4], QL[4];
            ldsm4(QH, sQh + aoff + kk * 32);
            ldsm4(QL, sQl + aoff + kk * 32);
#pragma unroll
            for (int n = 0; n < 8; n++) {
                uint32_t KB[4];
                ldsm4(KB, kvb + boff + (uint32_t)n * (16 * AST_B) + kk * 32);
                mma16816(sacc[2 * n],     QH, &KB[0]);
                mma16816(sacc[2 * n + 1], QH, &KB[2]);
                mma16816(sacc[2 * n],     QL, &KB[0]);
                mma16816(sacc[2 * n + 1], QL, &KB[2]);
                ldsm4(KB, kvb + ATILE_B + boff + (uint32_t)n * (16 * AST_B) + kk * 32);
                mma16816(sacc[2 * n],     QH, &KB[0]);
                mma16816(sacc[2 * n + 1], QH, &KB[2]);
            }
        }

        // ---- online softmax on fragments ----
        const float scale = 0.03125f;
        float mx0 = -1e30f, mx1 = -1e30f;
#pragma unroll
        for (int t = 0; t < 16; t++) {
            sacc[t][0] *= scale; sacc[t][1] *= scale;
            sacc[t][2] *= scale; sacc[t][3] *= scale;
            mx0 = fmaxf(mx0, fmaxf(sacc[t][0], sacc[t][1]));
            mx1 = fmaxf(mx1, fmaxf(sacc[t][2], sacc[t][3]));
        }
        mx0 = fmaxf(mx0, __shfl_xor_sync(0xffffffffu, mx0, 1));
        mx0 = fmaxf(mx0, __shfl_xor_sync(0xffffffffu, mx0, 2));
        mx1 = fmaxf(mx1, __shfl_xor_sync(0xffffffffu, mx1, 1));
        mx1 = fmaxf(mx1, __shfl_xor_sync(0xffffffffu, mx1, 2));
        const float mn0 = fmaxf(m0, mx0), mn1 = fmaxf(m1, mx1);
        const float a0 = __expf(m0 - mn0), a1 = __expf(m1 - mn1);
        float rs0 = 0.0f, rs1 = 0.0f;
#pragma unroll
        for (int t = 0; t < 16; t++) {
            float e0 = __expf(sacc[t][0] - mn0);
            float e1 = __expf(sacc[t][1] - mn0);
            float e2 = __expf(sacc[t][2] - mn1);
            float e3 = __expf(sacc[t][3] - mn1);
            sacc[t][0] = e0; sacc[t][1] = e1; sacc[t][2] = e2; sacc[t][3] = e3;
            rs0 += e0 + e1; rs1 += e2 + e3;
        }
        rs0 += __shfl_xor_sync(0xffffffffu, rs0, 1);
        rs0 += __shfl_xor_sync(0xffffffffu, rs0, 2);
        rs1 += __shfl_xor_sync(0xffffffffu, rs1, 1);
        rs1 += __shfl_xor_sync(0xffffffffu, rs1, 2);
        l0v = l0v * a0 + rs0;
        l1v = l1v * a1 + rs1;
        m0 = mn0; m1 = mn1;
#pragma unroll
        for (int j = 0; j < 8; j++) {
            ov[j][0] *= a0; ov[j][1] *= a0;
            ov[j][2] *= a1; ov[j][3] *= a1;
        }

        // ---- O += P V (3-pass), P packed from fragments ----
        const uint32_t sVh = kvb + 2 * ATILE_B, sVl = kvb + 3 * ATILE_B;
#pragma unroll
        for (int t = 0; t < 8; t++) {
            uint32_t aPh[4], aPl[4];
            hi_lo_pack(sacc[2 * t][0],     sacc[2 * t][1],     aPh[0], aPl[0]);
            hi_lo_pack(sacc[2 * t][2],     sacc[2 * t][3],     aPh[1], aPl[1]);
            hi_lo_pack(sacc[2 * t + 1][0], sacc[2 * t + 1][1], aPh[2], aPl[2]);
            hi_lo_pack(sacc[2 * t + 1][2], sacc[2 * t + 1][3], aPh[3], aPl[3]);
#pragma unroll
            for (int nv = 0; nv < 4; nv++) {
                uint32_t VB[4];
                ldsm4t(VB, sVh + voff + (uint32_t)t * (16 * AST_B) + nv * 32);
                mma16816(ov[2 * nv],     aPh, &VB[0]);
                mma16816(ov[2 * nv + 1], aPh, &VB[2]);
                mma16816(ov[2 * nv],     aPl, &VB[0]);
                mma16816(ov[2 * nv + 1], aPl, &VB[2]);
                ldsm4t(VB, sVl + voff + (uint32_t)t * (16 * AST_B) + nv * 32);
                mma16816(ov[2 * nv],     aPh, &VB[0]);
                mma16816(ov[2 * nv + 1], aPh, &VB[2]);
            }
        }

        __syncthreads();   // done reading stage kt&1
        if (kt + 2 < 8) {
            loadKV(kt + 2, kt & 1);
            CP_COMMIT();
            CP_WAIT(1);
            __syncthreads();
        } else if (kt + 1 < 8) {
            CP_WAIT(0);
            __syncthreads();
        }
    }

    // ---- epilogue ----
    const float inv0 = 1.0f / l0v, inv1 = 1.0f / l1v;
    const int gr = lid >> 2, gc = (lid & 3) * 2;
    float* op0 = O + (size_t)(b * NSEQ + q0 + 16 * wid + gr) * DDIM + h * DHEAD;
    float* op1 = op0 + 8 * DDIM;
#pragma unroll
    for (int j = 0; j < 8; j++) {
        *(float2*)(op0 + j * 8 + gc) = make_float2(ov[j][0] * inv0, ov[j][1] * inv0);
        *(float2*)(op1 + j * 8 + gc) = make_float2(ov[j][2] * inv1, ov[j][3] * inv1);
    }
}

// ============================ LayerNorm (+ optional bf16 split out) ==========
__global__ __launch_bounds__(256)
void ln_kernel(const float* __restrict__ A, const float* __restrict__ R,
               const float* __restrict__ gamma, const float* __restrict__ beta,
               float* __restrict__ out,
               __nv_bfloat16* __restrict__ hi, __nv_bfloat16* __restrict__ lo)
{
    const int row = blockIdx.x;
    const int tid = threadIdx.x;
    const size_t base = (size_t)row * DDIM + tid * 4;

    float4 v = *(const float4*)(A + base);
    if (R != nullptr) {
        float4 r = *(const float4*)(R + base);
        v.x += r.x; v.y += r.y; v.z += r.z; v.w += r.w;
    }

    __shared__ float red1[8];
    __shared__ float red2[8];

    float s = v.x + v.y + v.z + v.w;
#pragma unroll
    for (int off = 16; off > 0; off >>= 1) s += __shfl_xor_sync(0xffffffffu, s, off);
    if ((tid & 31) == 0) red1[tid >> 5] = s;
    __syncthreads();
    float tot = 0.0f;
#pragma unroll
    for (int k = 0; k < 8; k++) tot += red1[k];
    float mean = tot * (1.0f / 1024.0f);

    float d0 = v.x - mean, d1 = v.y - mean, d2 = v.z - mean, d3 = v.w - mean;
    float sq = d0 * d0 + d1 * d1 + d2 * d2 + d3 * d3;
#pragma unroll
    for (int off = 16; off > 0; off >>= 1) sq += __shfl_xor_sync(0xffffffffu, sq, off);
    if ((tid & 31) == 0) red2[tid >> 5] = sq;
    __syncthreads();
    float vtot = 0.0f;
#pragma unroll
    for (int k = 0; k < 8; k++) vtot += red2[k];
    float rstd = rsqrtf(vtot * (1.0f / 1024.0f) + 1e-6f);

    float4 g4 = *(const float4*)(gamma + tid * 4);
    float4 b4 = *(const float4*)(beta  + tid * 4);
    float4 o4 = make_float4(d0 * rstd * g4.x + b4.x,
                            d1 * rstd * g4.y + b4.y,
                            d2 * rstd * g4.z + b4.z,
                            d3 * rstd * g4.w + b4.w);
    *(float4*)(out + base) = o4;

    if (hi != nullptr) {
        uint32_t h01, l01, h23, l23;
        hi_lo_pack(o4.x, o4.y, h01, l01);
        hi_lo_pack(o4.z, o4.w, h23, l23);
        uint2 hw, lw;
        hw.x = h01; hw.y = h23;
        lw.x = l01; lw.y = l23;
        *(uint2*)(hi + base) = hw;
        *(uint2*)(lo + base) = lw;
    }
}

// ============================ host launch ====================================
extern "C" void kernel_launch(void* const* d_in, const int* in_sizes, int n_in,
                              void* d_out, int out_size)
{
    (void)in_sizes; (void)n_in; (void)out_size;
    const float* x  = (const float*)d_in[0];
    const float* y  = (const float*)d_in[1];
    const float* Wq = (const float*)d_in[2];
    const float* bq = (const float*)d_in[3];
    const float* Wk = (const float*)d_in[4];
    const float* bk = (const float*)d_in[5];
    const float* Wv = (const float*)d_in[6];
    const float* bv = (const float*)d_in[7];
    const float* Wf = (const float*)d_in[8];
    const float* bf = (const float*)d_in[9];
    const float* g1 = (const float*)d_in[10];
    const float* b1 = (const float*)d_in[11];
    const float* g2 = (const float*)d_in[12];
    const float* b2 = (const float*)d_in[13];
    float* out = (float*)d_out;

    float *pao, *ph1, *pt;
    cudaGetSymbolAddress((void**)&pao, g_ao);
    cudaGetSymbolAddress((void**)&ph1, g_h1);
    cudaGetSymbolAddress((void**)&pt,  g_t);

    void *paxh, *paxl, *payh, *payl, *pwth, *pwtl;
    void *pqh, *pql, *pkh, *pkl, *pvh, *pvl;
    cudaGetSymbolAddress(&paxh, g_axh);
    cudaGetSymbolAddress(&paxl, g_axl);
    cudaGetSymbolAddress(&payh, g_ayh);
    cudaGetSymbolAddress(&payl, g_ayl);
    cudaGetSymbolAddress(&pwth, g_wth);
    cudaGetSymbolAddress(&pwtl, g_wtl);
    cudaGetSymbolAddress(&pqh, g_qh);
    cudaGetSymbolAddress(&pql, g_ql);
    cudaGetSymbolAddress(&pkh, g_kh);
    cudaGetSymbolAddress(&pkl, g_kl);
    cudaGetSymbolAddress(&pvh, g_vh);
    cudaGetSymbolAddress(&pvl, g_vl);

    __nv_bfloat16* axh = (__nv_bfloat16*)paxh;
    __nv_bfloat16* axl = (__nv_bfloat16*)paxl;
    __nv_bfloat16* ayh = (__nv_bfloat16*)payh;
    __nv_bfloat16* ayl = (__nv_bfloat16*)payl;
    __nv_bfloat16* wth = (__nv_bfloat16*)pwth;
    __nv_bfloat16* wtl = (__nv_bfloat16*)pwtl;
    __nv_bfloat16* qh = (__nv_bfloat16*)pqh;
    __nv_bfloat16* ql = (__nv_bfloat16*)pql;
    __nv_bfloat16* kh = (__nv_bfloat16*)pkh;
    __nv_bfloat16* kl = (__nv_bfloat16*)pkl;
    __nv_bfloat16* vh = (__nv_bfloat16*)pvh;
    __nv_bfloat16* vl = (__nv_bfloat16*)pvl;
    const size_t WSZ = (size_t)DDIM * DDIM;

    cudaFuncSetAttribute(gemm_mma<0>, cudaFuncAttributeMaxDynamicSharedMemorySize, GSMEM);
    cudaFuncSetAttribute(gemm_mma<1>, cudaFuncAttributeMaxDynamicSharedMemorySize, GSMEM);
    cudaFuncSetAttribute(gemm_mma<2>, cudaFuncAttributeMaxDynamicSharedMemorySize, GSMEM);
    cudaFuncSetAttribute(attn_mma, cudaFuncAttributeMaxDynamicSharedMemorySize, ASMEM);

    const int split_grid = (MROWS * DDIM) / 4 / 256;  // 8192
    dim3 tgrid(32, 32), tblk(256);
    dim3 ggrid(DDIM / 128, MROWS / 128);               // (8, 64)

    // prep: splits + weight transposes
    split_kernel<<<split_grid, 256>>>(x, axh, axl);
    split_kernel<<<split_grid, 256>>>(y, ayh, ayl);
    tsplit_kernel<<<tgrid, tblk>>>(Wq, wth + 0 * WSZ, wtl + 0 * WSZ);
    tsplit_kernel<<<tgrid, tblk>>>(Wk, wth + 1 * WSZ, wtl + 1 * WSZ);
    tsplit_kernel<<<tgrid, tblk>>>(Wv, wth + 2 * WSZ, wtl + 2 * WSZ);
    tsplit_kernel<<<tgrid, tblk>>>(Wf, wth + 3 * WSZ, wtl + 3 * WSZ);

    // projections -> bf16 hi/lo directly
    gemm_mma<2><<<ggrid, 256, GSMEM>>>(axh, axl, wth + 0 * WSZ, wtl + 0 * WSZ, bq, nullptr, nullptr, qh, ql);
    gemm_mma<2><<<ggrid, 256, GSMEM>>>(ayh, ayl, wth + 1 * WSZ, wtl + 1 * WSZ, bk, nullptr, nullptr, kh, kl);
    gemm_mma<2><<<ggrid, 256, GSMEM>>>(ayh, ayl, wth + 2 * WSZ, wtl + 2 * WSZ, bv, nullptr, nullptr, vh, vl);

    // attention (tensor cores)
    attn_mma<<<dim3(NSEQ / 128, BB * NH), 256, ASMEM>>>(qh, ql, kh, kl, vh, vl, pao);

    // LN1(x + attn) -> fp32 h1 AND bf16 hi/lo split
    ln_kernel<<<MROWS, 256>>>(x, pao, g1, b1, ph1, axh, axl);

    // FF: t = relu(h1 @ Wf + bf) + h1
    gemm_mma<1><<<ggrid, 256, GSMEM>>>(axh, axl, wth + 3 * WSZ, wtl + 3 * WSZ, bf, ph1, pt, nullptr, nullptr);

    // LN2
    ln_kernel<<<MROWS, 256>>>(pt, nullptr, g2, b2, out, nullptr, nullptr);
}

// round 8
// speedup vs baseline: 2.8235x; 1.1564x over previous
#include <cuda_runtime.h>
#include <cuda_bf16.h>
#include <math.h>
#include <stdint.h>

// Problem constants
#define BB    8
#define NSEQ  1024
#define DDIM  1024
#define NH    16
#define DHEAD 64
#define MROWS (BB * NSEQ)   // 8192

// ============================ PTX helpers ====================================
__device__ __forceinline__ uint32_t smem_u32(const void* p) {
    uint32_t a;
    asm("{ .reg .u64 t; cvta.to.shared.u64 t, %1; cvt.u32.u64 %0, t; }" : "=r"(a) : "l"(p));
    return a;
}
__device__ __forceinline__ void cp16(uint32_t d, const void* s) {
    asm volatile("cp.async.cg.shared.global [%0], [%1], 16;" :: "r"(d), "l"(s) : "memory");
}
#define CP_COMMIT() asm volatile("cp.async.commit_group;" ::: "memory")
#define CP_WAIT(n)  asm volatile("cp.async.wait_group %0;" :: "n"(n) : "memory")

__device__ __forceinline__ void ldsm4(uint32_t* r, uint32_t a) {
    asm volatile("ldmatrix.sync.aligned.m8n8.x4.shared.b16 {%0,%1,%2,%3}, [%4];"
        : "=r"(r[0]), "=r"(r[1]), "=r"(r[2]), "=r"(r[3]) : "r"(a));
}
__device__ __forceinline__ void ldsm4t(uint32_t* r, uint32_t a) {
    asm volatile("ldmatrix.sync.aligned.m8n8.x4.trans.shared.b16 {%0,%1,%2,%3}, [%4];"
        : "=r"(r[0]), "=r"(r[1]), "=r"(r[2]), "=r"(r[3]) : "r"(a));
}
__device__ __forceinline__ void mma16816(float* c, const uint32_t* a, const uint32_t* b) {
    asm volatile("mma.sync.aligned.m16n8k16.row.col.f32.bf16.bf16.f32 "
        "{%0,%1,%2,%3}, {%4,%5,%6,%7}, {%8,%9}, {%0,%1,%2,%3};"
        : "+f"(c[0]), "+f"(c[1]), "+f"(c[2]), "+f"(c[3])
        : "r"(a[0]), "r"(a[1]), "r"(a[2]), "r"(a[3]), "r"(b[0]), "r"(b[1]));
}
__device__ __forceinline__ void hi_lo_pack(float x, float y, uint32_t& h, uint32_t& l) {
    __nv_bfloat16 hx = __float2bfloat16(x), hy = __float2bfloat16(y);
    __nv_bfloat16 lx = __float2bfloat16(x - __bfloat162float(hx));
    __nv_bfloat16 ly = __float2bfloat16(y - __bfloat162float(hy));
    __nv_bfloat162 hv(hx, hy), lv(lx, ly);
    h = *(uint32_t*)&hv; l = *(uint32_t*)&lv;
}

// ============================ scratch buffers ================================
__device__ float g_ao[(size_t)MROWS * DDIM];
__device__ float g_h1[(size_t)MROWS * DDIM];
__device__ float g_t [(size_t)MROWS * DDIM];

__device__ __align__(1024) __nv_bfloat16 g_axh[(size_t)MROWS * DDIM];
__device__ __align__(1024) __nv_bfloat16 g_axl[(size_t)MROWS * DDIM];
__device__ __align__(1024) __nv_bfloat16 g_ayh[(size_t)MROWS * DDIM];
__device__ __align__(1024) __nv_bfloat16 g_ayl[(size_t)MROWS * DDIM];
__device__ __align__(1024) __nv_bfloat16 g_wth[4][(size_t)DDIM * DDIM];
__device__ __align__(1024) __nv_bfloat16 g_wtl[4][(size_t)DDIM * DDIM];
__device__ __align__(1024) __nv_bfloat16 g_qh[(size_t)MROWS * DDIM];
__device__ __align__(1024) __nv_bfloat16 g_ql[(size_t)MROWS * DDIM];
__device__ __align__(1024) __nv_bfloat16 g_kh[(size_t)MROWS * DDIM];
__device__ __align__(1024) __nv_bfloat16 g_kl[(size_t)MROWS * DDIM];
__device__ __align__(1024) __nv_bfloat16 g_vh[(size_t)MROWS * DDIM];
__device__ __align__(1024) __nv_bfloat16 g_vl[(size_t)MROWS * DDIM];

// ============================ split / transpose ==============================
__global__ __launch_bounds__(256)
void split_kernel(const float* __restrict__ in,
                  __nv_bfloat16* __restrict__ hi, __nv_bfloat16* __restrict__ lo)
{
    int i = blockIdx.x * 256 + threadIdx.x;
    float4 v = ((const float4*)in)[i];
    __nv_bfloat16 h0 = __float2bfloat16(v.x), h1 = __float2bfloat16(v.y);
    __nv_bfloat16 h2 = __float2bfloat16(v.z), h3 = __float2bfloat16(v.w);
    __nv_bfloat16 l0 = __float2bfloat16(v.x - __bfloat162float(h0));
    __nv_bfloat16 l1 = __float2bfloat16(v.y - __bfloat162float(h1));
    __nv_bfloat16 l2 = __float2bfloat16(v.z - __bfloat162float(h2));
    __nv_bfloat16 l3 = __float2bfloat16(v.w - __bfloat162float(h3));
    __nv_bfloat162 ha(h0, h1), hb(h2, h3), la(l0, l1), lb(l2, l3);
    uint2 hw, lw;
    hw.x = *(uint32_t*)&ha; hw.y = *(uint32_t*)&hb;
    lw.x = *(uint32_t*)&la; lw.y = *(uint32_t*)&lb;
    ((uint2*)hi)[i] = hw;
    ((uint2*)lo)[i] = lw;
}

// W[k][n] fp32 -> Wt_hi/lo[n][k] bf16
__global__ __launch_bounds__(256)
void tsplit_kernel(const float* __restrict__ W,
                   __nv_bfloat16* __restrict__ th, __nv_bfloat16* __restrict__ tl)
{
    __shared__ float t[32][33];
    const int tx = threadIdx.x & 31;
    const int ty = threadIdx.x >> 5;
    const int kb = blockIdx.y * 32;
    const int nb = blockIdx.x * 32;
#pragma unroll
    for (int i = 0; i < 4; i++) {
        int kk = ty + i * 8;
        t[kk][tx] = W[(size_t)(kb + kk) * DDIM + nb + tx];
    }
    __syncthreads();
#pragma unroll
    for (int i = 0; i < 4; i++) {
        int nn = ty + i * 8;
        float v = t[tx][nn];
        __nv_bfloat16 h = __float2bfloat16(v);
        __nv_bfloat16 l = __float2bfloat16(v - __bfloat162float(h));
        size_t o = (size_t)(nb + nn) * DDIM + kb + tx;
        th[o] = h; tl[o] = l;
    }
}

// ============================ HMMA GEMM (bf16 split, fp32 acc) ===============
// BM=256, BN=128, BK=64, 256 threads, warp tile 64x64 (4m x 2n warps), 2 stages.
// EPI 0: C = A@W + b. EPI 1: C = relu(A@W+b)+res. EPI 2: bf16 hi/lo split out.
#define G_SST   144                      // smem row stride bytes (72 bf16)
#define G_ATILE (256 * G_SST)            // 36864
#define G_BTILE (128 * G_SST)            // 18432
#define G_STAGE (2 * G_ATILE + 2 * G_BTILE)   // 110592
#define GSMEM   (2 * G_STAGE)            // 221184

template <int EPI>
__global__ __launch_bounds__(256)
void gemm_mma(const __nv_bfloat16* __restrict__ Ah_, const __nv_bfloat16* __restrict__ Al_,
              const __nv_bfloat16* __restrict__ Bh_, const __nv_bfloat16* __restrict__ Bl_,
              const float* __restrict__ bias, const float* __restrict__ res,
              float* __restrict__ C,
              __nv_bfloat16* __restrict__ Ch, __nv_bfloat16* __restrict__ Cl)
{
    extern __shared__ __align__(128) char gsm[];
    const uint32_t sb = smem_u32(gsm);
    const int tid = threadIdx.x, lid = tid & 31, wid = tid >> 5;
    const int wm = (wid & 3) * 64, wn = (wid >> 2) * 64;
    const int bm = blockIdx.y * 256, bn = blockIdx.x * 128;

    // ldmatrix lane offsets
    const uint32_t aoff = (uint32_t)(wm + (lid & 15)) * G_SST + (((lid >> 4) & 1) * 16);
    const uint32_t boff = (uint32_t)(((lid >> 4) & 1) * 8 + (lid & 7)) * G_SST
                        + (((lid >> 3) & 1) * 16);

    float acc[4][8][4];
#pragma unroll
    for (int i = 0; i < 4; i++)
#pragma unroll
        for (int j = 0; j < 8; j++)
#pragma unroll
            for (int e = 0; e < 4; e++) acc[i][j][e] = 0.0f;

    auto LOAD = [&](int stg, int k0) {
        const uint32_t s = sb + (uint32_t)stg * G_STAGE;
#pragma unroll
        for (int t = 0; t < 8; t++) {           // A: 2048 cp16 per tensor
            int idx = tid + t * 256;
            int r = idx >> 3, sg = idx & 7;
            uint32_t so = (uint32_t)r * G_SST + sg * 16;
            size_t go = (size_t)(bm + r) * DDIM + k0 + sg * 8;
            cp16(s + so,           Ah_ + go);
            cp16(s + G_ATILE + so, Al_ + go);
        }
#pragma unroll
        for (int t = 0; t < 4; t++) {           // B: 1024 cp16 per tensor
            int idx = tid + t * 256;
            int r = idx >> 3, sg = idx & 7;
            uint32_t so = (uint32_t)r * G_SST + sg * 16;
            size_t go = (size_t)(bn + r) * DDIM + k0 + sg * 8;
            cp16(s + 2 * G_ATILE + so,           Bh_ + go);
            cp16(s + 2 * G_ATILE + G_BTILE + so, Bl_ + go);
        }
    };

    LOAD(0, 0);
    CP_COMMIT();

    for (int c = 0; c < 16; c++) {
        if (c + 1 < 16) { LOAD((c + 1) & 1, (c + 1) * 64); CP_COMMIT(); CP_WAIT(1); }
        else            { CP_WAIT(0); }
        __syncthreads();
        const uint32_t st = sb + (uint32_t)(c & 1) * G_STAGE;

#pragma unroll
        for (int s = 0; s < 4; s++) {
            const uint32_t ks = s * 32;          // 16 bf16 per k-step
            uint32_t AH[4][4], AL[4][4];
#pragma unroll
            for (int i = 0; i < 4; i++) {
                ldsm4(AH[i], st + aoff + (uint32_t)(i * 16) * G_SST + ks);
                ldsm4(AL[i], st + G_ATILE + aoff + (uint32_t)(i * 16) * G_SST + ks);
            }
#pragma unroll
            for (int g = 0; g < 4; g++) {
                uint32_t BH[4], BL[4];
                const uint32_t ba = st + 2 * G_ATILE
                                  + (uint32_t)(wn + g * 16) * G_SST + boff + ks;
                ldsm4(BH, ba);
                ldsm4(BL, ba + G_BTILE);
#pragma unroll
                for (int i = 0; i < 4; i++) {
                    mma16816(acc[i][2 * g],     AH[i], &BH[0]);
                    mma16816(acc[i][2 * g + 1], AH[i], &BH[2]);
                }
#pragma unroll
                for (int i = 0; i < 4; i++) {
                    mma16816(acc[i][2 * g],     AL[i], &BH[0]);
                    mma16816(acc[i][2 * g + 1], AL[i], &BH[2]);
                }
#pragma unroll
                for (int i = 0; i < 4; i++) {
                    mma16816(acc[i][2 * g],     AH[i], &BL[0]);
                    mma16816(acc[i][2 * g + 1], AH[i], &BL[2]);
                }
            }
        }
        __syncthreads();
    }

    // epilogue
    const int gr = lid >> 2, gc = (lid & 3) * 2;
#pragma unroll
    for (int i = 0; i < 4; i++) {
        const int r0 = bm + wm + i * 16 + gr;
        const int r1 = r0 + 8;
#pragma unroll
        for (int j = 0; j < 8; j++) {
            const int col = bn + wn + j * 8 + gc;
            const float bx = bias[col], by = bias[col + 1];
            float v0 = acc[i][j][0] + bx, v1 = acc[i][j][1] + by;
            float v2 = acc[i][j][2] + bx, v3 = acc[i][j][3] + by;
            if (EPI == 2) {
                uint32_t h01, l01, h23, l23;
                hi_lo_pack(v0, v1, h01, l01);
                hi_lo_pack(v2, v3, h23, l23);
                *(uint32_t*)(Ch + (size_t)r0 * DDIM + col) = h01;
                *(uint32_t*)(Cl + (size_t)r0 * DDIM + col) = l01;
                *(uint32_t*)(Ch + (size_t)r1 * DDIM + col) = h23;
                *(uint32_t*)(Cl + (size_t)r1 * DDIM + col) = l23;
            } else {
                if (EPI == 1) {
                    const float* rp0 = res + (size_t)r0 * DDIM + col;
                    const float* rp1 = res + (size_t)r1 * DDIM + col;
                    v0 = fmaxf(v0, 0.0f) + rp0[0];
                    v1 = fmaxf(v1, 0.0f) + rp0[1];
                    v2 = fmaxf(v2, 0.0f) + rp1[0];
                    v3 = fmaxf(v3, 0.0f) + rp1[1];
                }
                *(float2*)(C + (size_t)r0 * DDIM + col) = make_float2(v0, v1);
                *(float2*)(C + (size_t)r1 * DDIM + col) = make_float2(v2, v3);
            }
        }
    }
}

// ============================ HMMA flash attention ===========================
// CTA: 128 q-rows of one (b,h). 8 warps x 16 rows. K/V chunks of 128, 2-stage.
#define AST_B   144
#define ATILE_B (128 * AST_B)
#define ASMEM   (10 * ATILE_B)

__global__ __launch_bounds__(256, 1)
void attn_mma(const __nv_bfloat16* __restrict__ Qh_g, const __nv_bfloat16* __restrict__ Ql_g,
              const __nv_bfloat16* __restrict__ Kh_g, const __nv_bfloat16* __restrict__ Kl_g,
              const __nv_bfloat16* __restrict__ Vh_g, const __nv_bfloat16* __restrict__ Vl_g,
              float* __restrict__ O)
{
    extern __shared__ __align__(128) char asm_[];
    const uint32_t sb = smem_u32(asm_);
    const int tid = threadIdx.x, lid = tid & 31, wid = tid >> 5;
    const int bh = blockIdx.y, b = bh >> 4, h = bh & 15;
    const int q0 = blockIdx.x * 128;

    const size_t qbase = (size_t)(b * NSEQ + q0) * DDIM + h * DHEAD;
    const size_t kbase = (size_t)(b * NSEQ) * DDIM + h * DHEAD;

    const uint32_t sQh = sb, sQl = sb + ATILE_B;
    const uint32_t aoff = (uint32_t)(16 * wid + (lid & 15)) * AST_B + ((lid >> 4) & 1) * 16;
    const uint32_t boff = (uint32_t)(((lid >> 4) & 1) * 8 + (lid & 7)) * AST_B
                        + ((lid >> 3) & 1) * 16;
    const uint32_t voff = (uint32_t)(lid & 15) * AST_B + ((lid >> 4) & 1) * 16;

    auto loadKV = [&](int kt, int st) {
        const uint32_t base = sb + 2 * ATILE_B + (uint32_t)st * (4 * ATILE_B);
        const size_t gk = kbase + (size_t)(kt * 128) * DDIM;
        for (int i = tid; i < 1024; i += 256) {
            int r = i >> 3, sg = i & 7;
            uint32_t so = (uint32_t)r * AST_B + sg * 16;
            size_t go = gk + (size_t)r * DDIM + sg * 8;
            cp16(base + so,               Kh_g + go);
            cp16(base + ATILE_B + so,     Kl_g + go);
            cp16(base + 2 * ATILE_B + so, Vh_g + go);
            cp16(base + 3 * ATILE_B + so, Vl_g + go);
        }
    };

    for (int i = tid; i < 1024; i += 256) {
        int r = i >> 3, sg = i & 7;
        uint32_t so = (uint32_t)r * AST_B + sg * 16;
        size_t go = qbase + (size_t)r * DDIM + sg * 8;
        cp16(sQh + so, Qh_g + go);
        cp16(sQl + so, Ql_g + go);
    }
    loadKV(0, 0);
    CP_COMMIT();
    loadKV(1, 1);
    CP_COMMIT();
    CP_WAIT(1);
    __syncthreads();

    float m0 = -1e30f, m1 = -1e30f, l0v = 0.0f, l1v = 0.0f;
    float ov[8][4];
#pragma unroll
    for (int j = 0; j < 8; j++)
#pragma unroll
        for (int e = 0; e < 4; e++) ov[j][e] = 0.0f;

    for (int kt = 0; kt < 8; kt++) {
        const uint32_t kvb = sb + 2 * ATILE_B + (uint32_t)(kt & 1) * (4 * ATILE_B);

        float sacc[16][4];
#pragma unroll
        for (int t = 0; t < 16; t++)
#pragma unroll
            for (int e = 0; e < 4; e++) sacc[t][e] = 0.0f;

#pragma unroll
        for (int kk = 0; kk < 4; kk++) {
            uint32_t QH[4], QL[4];
            ldsm4(QH, sQh + aoff + kk * 32);
            ldsm4(QL, sQl + aoff + kk * 32);
#pragma unroll
            for (int n = 0; n < 8; n++) {
                uint32_t KB[4];
                ldsm4(KB, kvb + boff + (uint32_t)n * (16 * AST_B) + kk * 32);
                mma16816(sacc[2 * n],     QH, &KB[0]);
                mma16816(sacc[2 * n + 1], QH, &KB[2]);
                mma16816(sacc[2 * n],     QL, &KB[0]);
                mma16816(sacc[2 * n + 1], QL, &KB[2]);
                ldsm4(KB, kvb + ATILE_B + boff + (uint32_t)n * (16 * AST_B) + kk * 32);
                mma16816(sacc[2 * n],     QH, &KB[0]);
                mma16816(sacc[2 * n + 1], QH, &KB[2]);
            }
        }

        const float scale = 0.03125f;
        float mx0 = -1e30f, mx1 = -1e30f;
#pragma unroll
        for (int t = 0; t < 16; t++) {
            sacc[t][0] *= scale; sacc[t][1] *= scale;
            sacc[t][2] *= scale; sacc[t][3] *= scale;
            mx0 = fmaxf(mx0, fmaxf(sacc[t][0], sacc[t][1]));
            mx1 = fmaxf(mx1, fmaxf(sacc[t][2], sacc[t][3]));
        }
        mx0 = fmaxf(mx0, __shfl_xor_sync(0xffffffffu, mx0, 1));
        mx0 = fmaxf(mx0, __shfl_xor_sync(0xffffffffu, mx0, 2));
        mx1 = fmaxf(mx1, __shfl_xor_sync(0xffffffffu, mx1, 1));
        mx1 = fmaxf(mx1, __shfl_xor_sync(0xffffffffu, mx1, 2));
        const float mn0 = fmaxf(m0, mx0), mn1 = fmaxf(m1, mx1);
        const float a0 = __expf(m0 - mn0), a1 = __expf(m1 - mn1);
        float rs0 = 0.0f, rs1 = 0.0f;
#pragma unroll
        for (int t = 0; t < 16; t++) {
            float e0 = __expf(sacc[t][0] - mn0);
            float e1 = __expf(sacc[t][1] - mn0);
            float e2 = __expf(sacc[t][2] - mn1);
            float e3 = __expf(sacc[t][3] - mn1);
            sacc[t][0] = e0; sacc[t][1] = e1; sacc[t][2] = e2; sacc[t][3] = e3;
            rs0 += e0 + e1; rs1 += e2 + e3;
        }
        rs0 += __shfl_xor_sync(0xffffffffu, rs0, 1);
        rs0 += __shfl_xor_sync(0xffffffffu, rs0, 2);
        rs1 += __shfl_xor_sync(0xffffffffu, rs1, 1);
        rs1 += __shfl_xor_sync(0xffffffffu, rs1, 2);
        l0v = l0v * a0 + rs0;
        l1v = l1v * a1 + rs1;
        m0 = mn0; m1 = mn1;
#pragma unroll
        for (int j = 0; j < 8; j++) {
            ov[j][0] *= a0; ov[j][1] *= a0;
            ov[j][2] *= a1; ov[j][3] *= a1;
        }

        const uint32_t sVh = kvb + 2 * ATILE_B, sVl = kvb + 3 * ATILE_B;
#pragma unroll
        for (int t = 0; t < 8; t++) {
            uint32_t aPh[4], aPl[4];
            hi_lo_pack(sacc[2 * t][0],     sacc[2 * t][1],     aPh[0], aPl[0]);
            hi_lo_pack(sacc[2 * t][2],     sacc[2 * t][3],     aPh[1], aPl[1]);
            hi_lo_pack(sacc[2 * t + 1][0], sacc[2 * t + 1][1], aPh[2], aPl[2]);
            hi_lo_pack(sacc[2 * t + 1][2], sacc[2 * t + 1][3], aPh[3], aPl[3]);
#pragma unroll
            for (int nv = 0; nv < 4; nv++) {
                uint32_t VB[4];
                ldsm4t(VB, sVh + voff + (uint32_t)t * (16 * AST_B) + nv * 32);
                mma16816(ov[2 * nv],     aPh, &VB[0]);
                mma16816(ov[2 * nv + 1], aPh, &VB[2]);
                mma16816(ov[2 * nv],     aPl, &VB[0]);
                mma16816(ov[2 * nv + 1], aPl, &VB[2]);
                ldsm4t(VB, sVl + voff + (uint32_t)t * (16 * AST_B) + nv * 32);
                mma16816(ov[2 * nv],     aPh, &VB[0]);
                mma16816(ov[2 * nv + 1], aPh, &VB[2]);
            }
        }

        __syncthreads();
        if (kt + 2 < 8) {
            loadKV(kt + 2, kt & 1);
            CP_COMMIT();
            CP_WAIT(1);
            __syncthreads();
        } else if (kt + 1 < 8) {
            CP_WAIT(0);
            __syncthreads();
        }
    }

    const float inv0 = 1.0f / l0v, inv1 = 1.0f / l1v;
    const int gr = lid >> 2, gc = (lid & 3) * 2;
    float* op0 = O + (size_t)(b * NSEQ + q0 + 16 * wid + gr) * DDIM + h * DHEAD;
    float* op1 = op0 + 8 * DDIM;
#pragma unroll
    for (int j = 0; j < 8; j++) {
        *(float2*)(op0 + j * 8 + gc) = make_float2(ov[j][0] * inv0, ov[j][1] * inv0);
        *(float2*)(op1 + j * 8 + gc) = make_float2(ov[j][2] * inv1, ov[j][3] * inv1);
    }
}

// ============================ LayerNorm (+ optional bf16 split out) ==========
__global__ __launch_bounds__(256)
void ln_kernel(const float* __restrict__ A, const float* __restrict__ R,
               const float* __restrict__ gamma, const float* __restrict__ beta,
               float* __restrict__ out,
               __nv_bfloat16* __restrict__ hi, __nv_bfloat16* __restrict__ lo)
{
    const int row = blockIdx.x;
    const int tid = threadIdx.x;
    const size_t base = (size_t)row * DDIM + tid * 4;

    float4 v = *(const float4*)(A + base);
    if (R != nullptr) {
        float4 r = *(const float4*)(R + base);
        v.x += r.x; v.y += r.y; v.z += r.z; v.w += r.w;
    }

    __shared__ float red1[8];
    __shared__ float red2[8];

    float s = v.x + v.y + v.z + v.w;
#pragma unroll
    for (int off = 16; off > 0; off >>= 1) s += __shfl_xor_sync(0xffffffffu, s, off);
    if ((tid & 31) == 0) red1[tid >> 5] = s;
    __syncthreads();
    float tot = 0.0f;
#pragma unroll
    for (int k = 0; k < 8; k++) tot += red1[k];
    float mean = tot * (1.0f / 1024.0f);

    float d0 = v.x - mean, d1 = v.y - mean, d2 = v.z - mean, d3 = v.w - mean;
    float sq = d0 * d0 + d1 * d1 + d2 * d2 + d3 * d3;
#pragma unroll
    for (int off = 16; off > 0; off >>= 1) sq += __shfl_xor_sync(0xffffffffu, sq, off);
    if ((tid & 31) == 0) red2[tid >> 5] = sq;
    __syncthreads();
    float vtot = 0.0f;
#pragma unroll
    for (int k = 0; k < 8; k++) vtot += red2[k];
    float rstd = rsqrtf(vtot * (1.0f / 1024.0f) + 1e-6f);

    float4 g4 = *(const float4*)(gamma + tid * 4);
    float4 b4 = *(const float4*)(beta  + tid * 4);
    float4 o4 = make_float4(d0 * rstd * g4.x + b4.x,
                            d1 * rstd * g4.y + b4.y,
                            d2 * rstd * g4.z + b4.z,
                            d3 * rstd * g4.w + b4.w);
    *(float4*)(out + base) = o4;

    if (hi != nullptr) {
        uint32_t h01, l01, h23, l23;
        hi_lo_pack(o4.x, o4.y, h01, l01);
        hi_lo_pack(o4.z, o4.w, h23, l23);
        uint2 hw, lw;
        hw.x = h01; hw.y = h23;
        lw.x = l01; lw.y = l23;
        *(uint2*)(hi + base) = hw;
        *(uint2*)(lo + base) = lw;
    }
}

// ============================ host launch ====================================
extern "C" void kernel_launch(void* const* d_in, const int* in_sizes, int n_in,
                              void* d_out, int out_size)
{
    (void)in_sizes; (void)n_in; (void)out_size;
    const float* x  = (const float*)d_in[0];
    const float* y  = (const float*)d_in[1];
    const float* Wq = (const float*)d_in[2];
    const float* bq = (const float*)d_in[3];
    const float* Wk = (const float*)d_in[4];
    const float* bk = (const float*)d_in[5];
    const float* Wv = (const float*)d_in[6];
    const float* bv = (const float*)d_in[7];
    const float* Wf = (const float*)d_in[8];
    const float* bf = (const float*)d_in[9];
    const float* g1 = (const float*)d_in[10];
    const float* b1 = (const float*)d_in[11];
    const float* g2 = (const float*)d_in[12];
    const float* b2 = (const float*)d_in[13];
    float* out = (float*)d_out;

    float *pao, *ph1, *pt;
    cudaGetSymbolAddress((void**)&pao, g_ao);
    cudaGetSymbolAddress((void**)&ph1, g_h1);
    cudaGetSymbolAddress((void**)&pt,  g_t);

    void *paxh, *paxl, *payh, *payl, *pwth, *pwtl;
    void *pqh, *pql, *pkh, *pkl, *pvh, *pvl;
    cudaGetSymbolAddress(&paxh, g_axh);
    cudaGetSymbolAddress(&paxl, g_axl);
    cudaGetSymbolAddress(&payh, g_ayh);
    cudaGetSymbolAddress(&payl, g_ayl);
    cudaGetSymbolAddress(&pwth, g_wth);
    cudaGetSymbolAddress(&pwtl, g_wtl);
    cudaGetSymbolAddress(&pqh, g_qh);
    cudaGetSymbolAddress(&pql, g_ql);
    cudaGetSymbolAddress(&pkh, g_kh);
    cudaGetSymbolAddress(&pkl, g_kl);
    cudaGetSymbolAddress(&pvh, g_vh);
    cudaGetSymbolAddress(&pvl, g_vl);

    __nv_bfloat16* axh = (__nv_bfloat16*)paxh;
    __nv_bfloat16* axl = (__nv_bfloat16*)paxl;
    __nv_bfloat16* ayh = (__nv_bfloat16*)payh;
    __nv_bfloat16* ayl = (__nv_bfloat16*)payl;
    __nv_bfloat16* wth = (__nv_bfloat16*)pwth;
    __nv_bfloat16* wtl = (__nv_bfloat16*)pwtl;
    __nv_bfloat16* qh = (__nv_bfloat16*)pqh;
    __nv_bfloat16* ql = (__nv_bfloat16*)pql;
    __nv_bfloat16* kh = (__nv_bfloat16*)pkh;
    __nv_bfloat16* kl = (__nv_bfloat16*)pkl;
    __nv_bfloat16* vh = (__nv_bfloat16*)pvh;
    __nv_bfloat16* vl = (__nv_bfloat16*)pvl;
    const size_t WSZ = (size_t)DDIM * DDIM;

    cudaFuncSetAttribute(gemm_mma<0>, cudaFuncAttributeMaxDynamicSharedMemorySize, GSMEM);
    cudaFuncSetAttribute(gemm_mma<1>, cudaFuncAttributeMaxDynamicSharedMemorySize, GSMEM);
    cudaFuncSetAttribute(gemm_mma<2>, cudaFuncAttributeMaxDynamicSharedMemorySize, GSMEM);
    cudaFuncSetAttribute(attn_mma, cudaFuncAttributeMaxDynamicSharedMemorySize, ASMEM);

    const int split_grid = (MROWS * DDIM) / 4 / 256;  // 8192
    dim3 tgrid(32, 32), tblk(256);
    dim3 ggrid(DDIM / 128, MROWS / 256);               // (8, 32)

    // prep: splits + weight transposes
    split_kernel<<<split_grid, 256>>>(x, axh, axl);
    split_kernel<<<split_grid, 256>>>(y, ayh, ayl);
    tsplit_kernel<<<tgrid, tblk>>>(Wq, wth + 0 * WSZ, wtl + 0 * WSZ);
    tsplit_kernel<<<tgrid, tblk>>>(Wk, wth + 1 * WSZ, wtl + 1 * WSZ);
    tsplit_kernel<<<tgrid, tblk>>>(Wv, wth + 2 * WSZ, wtl + 2 * WSZ);
    tsplit_kernel<<<tgrid, tblk>>>(Wf, wth + 3 * WSZ, wtl + 3 * WSZ);

    // projections -> bf16 hi/lo directly
    gemm_mma<2><<<ggrid, 256, GSMEM>>>(axh, axl, wth + 0 * WSZ, wtl + 0 * WSZ, bq, nullptr, nullptr, qh, ql);
    gemm_mma<2><<<ggrid, 256, GSMEM>>>(ayh, ayl, wth + 1 * WSZ, wtl + 1 * WSZ, bk, nullptr, nullptr, kh, kl);
    gemm_mma<2><<<ggrid, 256, GSMEM>>>(ayh, ayl, wth + 2 * WSZ, wtl + 2 * WSZ, bv, nullptr, nullptr, vh, vl);

    // attention (tensor cores)
    attn_mma<<<dim3(NSEQ / 128, BB * NH), 256, ASMEM>>>(qh, ql, kh, kl, vh, vl, pao);

    // LN1(x + attn) -> fp32 h1 AND bf16 hi/lo split
    ln_kernel<<<MROWS, 256>>>(x, pao, g1, b1, ph1, axh, axl);

    // FF: t = relu(h1 @ Wf + bf) + h1
    gemm_mma<1><<<ggrid, 256, GSMEM>>>(axh, axl, wth + 3 * WSZ, wtl + 3 * WSZ, bf, ph1, pt, nullptr, nullptr);

    // LN2
    ln_kernel<<<MROWS, 256>>>(pt, nullptr, g2, b2, out, nullptr, nullptr);
}